// round 1
// baseline (speedup 1.0000x reference)
#include <cuda_runtime.h>

// ---------------- problem sizes ----------------
#define NC 100000
#define NT 300000
#define NP 50000
#define NF 8
#define DIMC 16
#define D 128
#define EM 300000
#define EI 600000
#define NOUT 10

// ---------------- scratch (static device globals; allocation-free) ----------------
__device__ float g_hc[2][(size_t)NC * D];
__device__ float g_ht[2][(size_t)NT * D];
__device__ float g_hp[2][(size_t)NP * D];
__device__ float g_msg[(size_t)NT * D];
__device__ float g_inv_mt[NT];  // 1/max(deg,1) : transaction via makes-edges
__device__ float g_inv_mc[NC];  // customer via makes-edges (reverse)
__device__ float g_inv_it[NT];  // transaction via in-edges
__device__ float g_inv_ip[NP];  // product via in-edges (reverse)

// ---------------- small kernels ----------------
__global__ void zero_f4(float4* __restrict__ p, int n4) {
    int i = blockIdx.x * blockDim.x + threadIdx.x;
    if (i < n4) p[i] = make_float4(0.f, 0.f, 0.f, 0.f);
}

// h[n, f*16+d] = x[n,f] * W[f,d] + b[f,d]   (W,b: 128 floats per table)
__global__ void embed_kernel(const float* __restrict__ x,
                             const float* __restrict__ W,
                             const float* __restrict__ b,
                             float* __restrict__ h, int n) {
    int idx = blockIdx.x * blockDim.x + threadIdx.x;
    if (idx >= n * D) return;
    int row = idx >> 7;
    int col = idx & 127;
    int f   = col >> 4;
    h[idx] = fmaf(x[row * NF + f], W[col], b[col]);
}

__global__ void count_edges(const int* __restrict__ dst, int E, float* __restrict__ cnt) {
    int e = blockIdx.x * blockDim.x + threadIdx.x;
    if (e < E) atomicAdd(cnt + dst[e], 1.0f);
}

__global__ void make_inv(float* __restrict__ cnt, int n) {
    int i = blockIdx.x * blockDim.x + threadIdx.x;
    if (i < n) cnt[i] = 1.0f / fmaxf(cnt[i], 1.0f);
}

// vectored global reduction (sm_90+): 4 floats per instruction
__device__ __forceinline__ void red_add_v4(float* addr, float4 v) {
    asm volatile("red.global.add.v4.f32 [%0], {%1,%2,%3,%4};"
                 :: "l"(addr), "f"(v.x), "f"(v.y), "f"(v.z), "f"(v.w)
                 : "memory");
}

// one warp per edge: gather 512B row of h_src, scatter-add into msg[dst]
__global__ void scatter_kernel(const float* __restrict__ hsrc,
                               const int* __restrict__ src,
                               const int* __restrict__ dst,
                               int E, float* __restrict__ msg) {
    int e    = (blockIdx.x * blockDim.x + threadIdx.x) >> 5;
    int lane = threadIdx.x & 31;
    if (e >= E) return;
    int s = src[e];
    int d = dst[e];
    float4 v = ((const float4*)(hsrc + (size_t)s * D))[lane];
    red_add_v4(msg + (size_t)d * D + lane * 4, v);
}

// ---------------- fused SAGE GEMM ----------------
// out = alpha * ( (msg*inv) @ Wn + hdst @ Wr + bias + (accum ? accum : 0) )
// Wn, Wr resident in shared (128KB); 64-row tiles; thread tile 8 rows x 4 cols.
#define TILE_ROWS 64
#define GEMM_SMEM ((16384 + 16384 + 8192 + 8192) * 4)  // 192 KB

__global__ __launch_bounds__(256)
void sage_gemm(const float* __restrict__ msg, const float* __restrict__ inv,
               const float* __restrict__ hdst,
               const float* __restrict__ Wn, const float* __restrict__ Wr,
               const float* __restrict__ bias,
               const float* __restrict__ accum, float alpha,
               float* __restrict__ out, int n) {
    extern __shared__ float sm[];
    float* Wn_s = sm;                 // 128*128
    float* Wr_s = sm + 16384;         // 128*128
    float* A_s  = sm + 32768;         // 64*128 (mean)
    float* B_s  = sm + 32768 + 8192;  // 64*128 (root)

    const int tid = threadIdx.x;
    const int r = tid >> 5;   // 0..7  : row group (8 rows each)
    const int c = tid & 31;   // 0..31 : col group (4 cols each)

    // stage weights once per block
    {
        const float4* wn4 = (const float4*)Wn;
        const float4* wr4 = (const float4*)Wr;
        float4* sn = (float4*)Wn_s;
        float4* sr = (float4*)Wr_s;
        for (int i = tid; i < 4096; i += 256) { sn[i] = wn4[i]; sr[i] = wr4[i]; }
    }
    const float4 bi = ((const float4*)bias)[c];

    const int ntiles = (n + TILE_ROWS - 1) / TILE_ROWS;
    for (int t = blockIdx.x; t < ntiles; t += gridDim.x) {
        const int row0 = t * TILE_ROWS;
        __syncthreads();
        // stage A (mean = msg*inv) and B (hdst): 2048 float4 each
        for (int i = tid; i < 2048; i += 256) {
            int rr  = i >> 5;
            int col = i & 31;
            int row = row0 + rr;
            float4 a, b;
            if (row < n) {
                a = ((const float4*)msg)[(size_t)row * 32 + col];
                float iv = inv[row];
                a.x *= iv; a.y *= iv; a.z *= iv; a.w *= iv;
                b = ((const float4*)hdst)[(size_t)row * 32 + col];
            } else {
                a = make_float4(0.f, 0.f, 0.f, 0.f);
                b = a;
            }
            ((float4*)A_s)[i] = a;
            ((float4*)B_s)[i] = b;
        }
        __syncthreads();

        float acc[8][4];
        #pragma unroll
        for (int i = 0; i < 8; i++)
            #pragma unroll
            for (int j = 0; j < 4; j++) acc[i][j] = 0.f;

        const float4* A4  = (const float4*)A_s;
        const float4* B4  = (const float4*)B_s;
        const float4* WN4 = (const float4*)Wn_s;
        const float4* WR4 = (const float4*)Wr_s;

        #pragma unroll 2
        for (int k4 = 0; k4 < 32; k4++) {
            float4 wn[4], wr[4];
            #pragma unroll
            for (int j = 0; j < 4; j++) {
                wn[j] = WN4[(k4 * 4 + j) * 32 + c];
                wr[j] = WR4[(k4 * 4 + j) * 32 + c];
            }
            #pragma unroll
            for (int i = 0; i < 8; i++) {
                float4 a = A4[(r * 8 + i) * 32 + k4];
                float4 b = B4[(r * 8 + i) * 32 + k4];
                acc[i][0] += a.x*wn[0].x + a.y*wn[1].x + a.z*wn[2].x + a.w*wn[3].x
                           + b.x*wr[0].x + b.y*wr[1].x + b.z*wr[2].x + b.w*wr[3].x;
                acc[i][1] += a.x*wn[0].y + a.y*wn[1].y + a.z*wn[2].y + a.w*wn[3].y
                           + b.x*wr[0].y + b.y*wr[1].y + b.z*wr[2].y + b.w*wr[3].y;
                acc[i][2] += a.x*wn[0].z + a.y*wn[1].z + a.z*wn[2].z + a.w*wn[3].z
                           + b.x*wr[0].z + b.y*wr[1].z + b.z*wr[2].z + b.w*wr[3].z;
                acc[i][3] += a.x*wn[0].w + a.y*wn[1].w + a.z*wn[2].w + a.w*wn[3].w
                           + b.x*wr[0].w + b.y*wr[1].w + b.z*wr[2].w + b.w*wr[3].w;
            }
        }

        #pragma unroll
        for (int i = 0; i < 8; i++) {
            int row = row0 + r * 8 + i;
            if (row < n) {
                float4 o;
                o.x = acc[i][0] + bi.x;
                o.y = acc[i][1] + bi.y;
                o.z = acc[i][2] + bi.z;
                o.w = acc[i][3] + bi.w;
                if (accum) {
                    float4 av = ((const float4*)accum)[(size_t)row * 32 + c];
                    o.x += av.x; o.y += av.y; o.z += av.z; o.w += av.w;
                }
                o.x *= alpha; o.y *= alpha; o.z *= alpha; o.w *= alpha;
                ((float4*)out)[(size_t)row * 32 + c] = o;
            }
        }
    }
}

// ---------------- output head: logits @ [128,10] + softmax ----------------
__global__ void out_softmax(const float* __restrict__ ht,
                            const float* __restrict__ Wout,
                            const float* __restrict__ bout,
                            float* __restrict__ out, int n) {
    int row  = (blockIdx.x * blockDim.x + threadIdx.x) >> 5;
    int lane = threadIdx.x & 31;
    if (row >= n) return;
    float4 h4 = ((const float4*)(ht + (size_t)row * D))[lane];
    float h[4] = {h4.x, h4.y, h4.z, h4.w};
    float p[NOUT];
    #pragma unroll
    for (int cc = 0; cc < NOUT; cc++) {
        float s = 0.f;
        #pragma unroll
        for (int j = 0; j < 4; j++) s += h[j] * Wout[(lane * 4 + j) * NOUT + cc];
        #pragma unroll
        for (int o = 16; o > 0; o >>= 1) s += __shfl_xor_sync(0xffffffffu, s, o);
        p[cc] = s + bout[cc];
    }
    if (lane == 0) {
        float m = p[0];
        #pragma unroll
        for (int cc = 1; cc < NOUT; cc++) m = fmaxf(m, p[cc]);
        float sum = 0.f;
        #pragma unroll
        for (int cc = 0; cc < NOUT; cc++) { p[cc] = expf(p[cc] - m); sum += p[cc]; }
        float isum = 1.0f / sum;
        #pragma unroll
        for (int cc = 0; cc < NOUT; cc++) out[(size_t)row * NOUT + cc] = p[cc] * isum;
    }
}

// ---------------- host orchestration ----------------
static inline void zero_buf(float* p, size_t nfloats) {
    int n4 = (int)(nfloats / 4);
    zero_f4<<<(n4 + 255) / 256, 256>>>((float4*)p, n4);
}

extern "C" void kernel_launch(void* const* d_in, const int* in_sizes, int n_in,
                              void* d_out, int out_size) {
    const float* x_c   = (const float*)d_in[0];
    const float* x_t   = (const float*)d_in[1];
    const float* x_p   = (const float*)d_in[2];
    const float* W_col = (const float*)d_in[3];
    const float* b_col = (const float*)d_in[4];
    const float* Wn    = (const float*)d_in[5];
    const float* Wr    = (const float*)d_in[6];
    const float* b_lin = (const float*)d_in[7];
    const float* W_out = (const float*)d_in[8];
    const float* b_out = (const float*)d_in[9];
    const int* em_src  = (const int*)d_in[10];
    const int* em_dst  = (const int*)d_in[11];
    const int* ei_src  = (const int*)d_in[12];
    const int* ei_dst  = (const int*)d_in[13];
    float* out = (float*)d_out;

    float *hc_base, *ht_base, *hp_base, *msg, *inv_mt, *inv_mc, *inv_it, *inv_ip;
    cudaGetSymbolAddress((void**)&hc_base, g_hc);
    cudaGetSymbolAddress((void**)&ht_base, g_ht);
    cudaGetSymbolAddress((void**)&hp_base, g_hp);
    cudaGetSymbolAddress((void**)&msg,     g_msg);
    cudaGetSymbolAddress((void**)&inv_mt,  g_inv_mt);
    cudaGetSymbolAddress((void**)&inv_mc,  g_inv_mc);
    cudaGetSymbolAddress((void**)&inv_it,  g_inv_it);
    cudaGetSymbolAddress((void**)&inv_ip,  g_inv_ip);
    float* hc[2] = {hc_base, hc_base + (size_t)NC * D};
    float* ht[2] = {ht_base, ht_base + (size_t)NT * D};
    float* hp[2] = {hp_base, hp_base + (size_t)NP * D};

    cudaFuncSetAttribute(sage_gemm, cudaFuncAttributeMaxDynamicSharedMemorySize, GEMM_SMEM);

    // ---- per-column embeddings ----
    embed_kernel<<<(NC * D + 255) / 256, 256>>>(x_c, W_col + 0,       b_col + 0,       hc[0], NC);
    embed_kernel<<<(NT * D + 255) / 256, 256>>>(x_t, W_col + D,       b_col + D,       ht[0], NT);
    embed_kernel<<<(NP * D + 255) / 256, 256>>>(x_p, W_col + 2 * D,   b_col + 2 * D,   hp[0], NP);

    // ---- degree inverses (fixed per launch) ----
    zero_buf(inv_mt, NT); zero_buf(inv_mc, NC); zero_buf(inv_it, NT); zero_buf(inv_ip, NP);
    count_edges<<<(EM + 255) / 256, 256>>>(em_dst, EM, inv_mt);
    count_edges<<<(EM + 255) / 256, 256>>>(em_src, EM, inv_mc);
    count_edges<<<(EI + 255) / 256, 256>>>(ei_dst, EI, inv_it);
    count_edges<<<(EI + 255) / 256, 256>>>(ei_src, EI, inv_ip);
    make_inv<<<(NT + 255) / 256, 256>>>(inv_mt, NT);
    make_inv<<<(NC + 255) / 256, 256>>>(inv_mc, NC);
    make_inv<<<(NT + 255) / 256, 256>>>(inv_it, NT);
    make_inv<<<(NP + 255) / 256, 256>>>(inv_ip, NP);

    const int GB = 148;  // one 192KB-smem CTA per SM; grid-stride over tiles
    int cur = 0;
    for (int l = 0; l < 2; l++) {
        int nxt = 1 - cur;
        const size_t WSZ = (size_t)D * D;
        // R0: customer -makes-> transaction  (out -> ht[nxt])
        zero_buf(msg, (size_t)NT * D);
        scatter_kernel<<<(EM * 32 + 255) / 256, 256>>>(hc[cur], em_src, em_dst, EM, msg);
        sage_gemm<<<GB, 256, GEMM_SMEM>>>(msg, inv_mt, ht[cur],
                                          Wn + (l * 4 + 0) * WSZ, Wr + (l * 4 + 0) * WSZ,
                                          b_lin + (l * 4 + 0) * D,
                                          nullptr, 1.0f, ht[nxt], NT);
        // R2: product -in-> transaction  (ht[nxt] = 0.5*(o_t0 + o_t2))
        zero_buf(msg, (size_t)NT * D);
        scatter_kernel<<<(EI * 32 + 255) / 256, 256>>>(hp[cur], ei_src, ei_dst, EI, msg);
        sage_gemm<<<GB, 256, GEMM_SMEM>>>(msg, inv_it, ht[cur],
                                          Wn + (l * 4 + 2) * WSZ, Wr + (l * 4 + 2) * WSZ,
                                          b_lin + (l * 4 + 2) * D,
                                          ht[nxt], 0.5f, ht[nxt], NT);
        // R1: transaction -rev_makes-> customer
        zero_buf(msg, (size_t)NC * D);
        scatter_kernel<<<(EM * 32 + 255) / 256, 256>>>(ht[cur], em_dst, em_src, EM, msg);
        sage_gemm<<<GB, 256, GEMM_SMEM>>>(msg, inv_mc, hc[cur],
                                          Wn + (l * 4 + 1) * WSZ, Wr + (l * 4 + 1) * WSZ,
                                          b_lin + (l * 4 + 1) * D,
                                          nullptr, 1.0f, hc[nxt], NC);
        // R3: transaction -rev_in-> product
        zero_buf(msg, (size_t)NP * D);
        scatter_kernel<<<(EI * 32 + 255) / 256, 256>>>(ht[cur], ei_dst, ei_src, EI, msg);
        sage_gemm<<<GB, 256, GEMM_SMEM>>>(msg, inv_ip, hp[cur],
                                          Wn + (l * 4 + 3) * WSZ, Wr + (l * 4 + 3) * WSZ,
                                          b_lin + (l * 4 + 3) * D,
                                          nullptr, 1.0f, hp[nxt], NP);
        cur = nxt;
    }

    // ---- output head ----
    out_softmax<<<(NT * 32 + 255) / 256, 256>>>(ht[cur], W_out, b_out, out, NT);
}

// round 2
// speedup vs baseline: 1.2492x; 1.2492x over previous
#include <cuda_runtime.h>

// ---------------- problem sizes ----------------
#define NC 100000
#define NT 300000
#define NP 50000
#define NF 8
#define DIMC 16
#define D 128
#define EM 300000
#define EI 600000
#define NOUT 10

typedef unsigned long long ull;

// ---------------- scratch (static device globals; allocation-free) ----------------
__device__ float g_hc[2][(size_t)NC * D];
__device__ float g_ht[2][(size_t)NT * D];
__device__ float g_hp[2][(size_t)NP * D];
__device__ float g_msg[(size_t)NT * D];
__device__ float g_inv_mt[NT];
__device__ float g_inv_mc[NC];
__device__ float g_inv_it[NT];
__device__ float g_inv_ip[NP];
// combined transaction weights: per layer [Wn0h | Wn2h | Wr02 | b02]
#define WT_STRIDE (3 * 16384 + 128)
__device__ float g_wt[2][WT_STRIDE];

// ---------------- small kernels ----------------
__global__ void zero_f4(float4* __restrict__ p, int n4) {
    int i = blockIdx.x * blockDim.x + threadIdx.x;
    if (i < n4) p[i] = make_float4(0.f, 0.f, 0.f, 0.f);
}

__global__ void embed_kernel(const float* __restrict__ x,
                             const float* __restrict__ W,
                             const float* __restrict__ b,
                             float* __restrict__ h, int n) {
    int idx = blockIdx.x * blockDim.x + threadIdx.x;
    if (idx >= n * D) return;
    int row = idx >> 7;
    int col = idx & 127;
    int f   = col >> 4;
    h[idx] = fmaf(x[row * NF + f], W[col], b[col]);
}

__global__ void count_edges(const int* __restrict__ dst, int E, float* __restrict__ cnt) {
    int e = blockIdx.x * blockDim.x + threadIdx.x;
    if (e < E) atomicAdd(cnt + dst[e], 1.0f);
}

__global__ void make_inv(float* __restrict__ cnt, int n) {
    int i = blockIdx.x * blockDim.x + threadIdx.x;
    if (i < n) cnt[i] = 1.0f / fmaxf(cnt[i], 1.0f);
}

// combined transaction weights: Wn0h=0.5*Wn0, Wn2h=0.5*Wn2, Wr02=0.5*(Wr0+Wr2), b02=0.5*(b0+b2)
__global__ void prep_weights(const float* __restrict__ Wn, const float* __restrict__ Wr,
                             const float* __restrict__ b_lin) {
    int i = blockIdx.x * blockDim.x + threadIdx.x;
    if (i >= 16384) return;
    #pragma unroll
    for (int l = 0; l < 2; l++) {
        float* base = g_wt[l];
        base[i]           = 0.5f * Wn[(l * 4 + 0) * 16384 + i];
        base[16384 + i]   = 0.5f * Wn[(l * 4 + 2) * 16384 + i];
        base[32768 + i]   = 0.5f * (Wr[(l * 4 + 0) * 16384 + i] + Wr[(l * 4 + 2) * 16384 + i]);
        if (i < 128)
            base[49152 + i] = 0.5f * (b_lin[(l * 4 + 0) * 128 + i] + b_lin[(l * 4 + 2) * 128 + i]);
    }
}

__device__ __forceinline__ void red_add_v4(float* addr, float4 v) {
    asm volatile("red.global.add.v4.f32 [%0], {%1,%2,%3,%4};"
                 :: "l"(addr), "f"(v.x), "f"(v.y), "f"(v.z), "f"(v.w)
                 : "memory");
}

__global__ void scatter_kernel(const float* __restrict__ hsrc,
                               const int* __restrict__ src,
                               const int* __restrict__ dst,
                               int E, float* __restrict__ msg) {
    int e    = (blockIdx.x * blockDim.x + threadIdx.x) >> 5;
    int lane = threadIdx.x & 31;
    if (e >= E) return;
    int s = src[e];
    int d = dst[e];
    float4 v = ((const float4*)(hsrc + (size_t)s * D))[lane];
    red_add_v4(msg + (size_t)d * D + lane * 4, v);
}

// ---------------- f32x2 SAGE GEMM ----------------
// out = (msg*inv)@W1 [+ hdst@W2 + bias] [+ accum]
// W staged in smem as K-pair-packed f32x2 (transposed: Wp[k2][col]).
// A,B staged row-major (k-contiguous) -> natural f32x2 K-pairs.
// Thread tile: 4 rows x 8 cols (cols strided by 16). Tile: 64 rows.
#define ASTRIDE 132                     // floats per A_s/B_s row (pad for banks)
#define GEMM_SMEM ((16384 + 16384 + 64 * ASTRIDE * 2) * 4)  // 198656 B

#define FMA2(acc, a, w) asm("fma.rn.f32x2 %0, %1, %2, %0;" : "+l"(acc) : "l"(a), "l"(w))

__device__ __forceinline__ ull pack2(float lo, float hi) {
    ull p;
    asm("mov.b64 %0, {%1, %2};" : "=l"(p) : "f"(lo), "f"(hi));
    return p;
}
__device__ __forceinline__ float2 unpack2(ull p) {
    float lo, hi;
    asm("mov.b64 {%0, %1}, %2;" : "=f"(lo), "=f"(hi) : "l"(p));
    return make_float2(lo, hi);
}

template <bool HASB, bool HASACC>
__global__ __launch_bounds__(256)
void sage_gemm2(const float* __restrict__ msg, const float* __restrict__ inv,
                const float* __restrict__ hdst,
                const float* __restrict__ W1, const float* __restrict__ W2,
                const float* __restrict__ bias,
                const float* __restrict__ accum,
                float* __restrict__ out, int n) {
    extern __shared__ float sm[];
    ull*   Wp1 = (ull*)sm;                       // 64 k2-rows x 128 cols
    ull*   Wp2 = (ull*)(sm + 16384);
    float* A_s = sm + 32768;                     // 64 x ASTRIDE
    float* B_s = A_s + 64 * ASTRIDE;

    const int tid = threadIdx.x;

    // stage weights as K-pair f32x2, column-indexed
    for (int i = tid; i < 8192; i += 256) {
        int k2  = i >> 7;
        int col = i & 127;
        Wp1[i] = pack2(W1[(2 * k2) * 128 + col], W1[(2 * k2 + 1) * 128 + col]);
        if (HASB)
            Wp2[i] = pack2(W2[(2 * k2) * 128 + col], W2[(2 * k2 + 1) * 128 + col]);
    }

    const int c = tid & 15;   // col group: cols c, c+16, ..., c+112
    const int r = tid >> 4;   // row group: rows r*4 .. r*4+3

    float bi[8];
    if (HASB) {
        #pragma unroll
        for (int j = 0; j < 8; j++) bi[j] = bias[c + 16 * j];
    }

    const int ntiles = (n + 63) >> 6;
    for (int t = blockIdx.x; t < ntiles; t += gridDim.x) {
        const int row0 = t << 6;
        __syncthreads();
        for (int i = tid; i < 2048; i += 256) {
            int rr   = i >> 5;
            int col4 = i & 31;
            int row  = row0 + rr;
            float4 a, b;
            if (row < n) {
                a = ((const float4*)msg)[(size_t)row * 32 + col4];
                float iv = inv[row];
                a.x *= iv; a.y *= iv; a.z *= iv; a.w *= iv;
                if (HASB) b = ((const float4*)hdst)[(size_t)row * 32 + col4];
            } else {
                a = make_float4(0.f, 0.f, 0.f, 0.f);
                b = a;
            }
            ((float4*)(A_s + rr * ASTRIDE))[col4] = a;
            if (HASB) ((float4*)(B_s + rr * ASTRIDE))[col4] = b;
        }
        __syncthreads();

        ull acc[4][8];
        #pragma unroll
        for (int i = 0; i < 4; i++)
            #pragma unroll
            for (int j = 0; j < 8; j++) acc[i][j] = 0ull;

        const float* Abase = A_s + (r * 4) * ASTRIDE;
        const float* Bbase = B_s + (r * 4) * ASTRIDE;

        #pragma unroll 2
        for (int k2 = 0; k2 < 64; k2++) {
            ull w1[8], a[4];
            #pragma unroll
            for (int j = 0; j < 8; j++) w1[j] = Wp1[k2 * 128 + c + 16 * j];
            #pragma unroll
            for (int i = 0; i < 4; i++) a[i] = *(const ull*)(Abase + i * ASTRIDE + 2 * k2);
            #pragma unroll
            for (int i = 0; i < 4; i++)
                #pragma unroll
                for (int j = 0; j < 8; j++) FMA2(acc[i][j], a[i], w1[j]);
            if (HASB) {
                ull w2[8], b[4];
                #pragma unroll
                for (int j = 0; j < 8; j++) w2[j] = Wp2[k2 * 128 + c + 16 * j];
                #pragma unroll
                for (int i = 0; i < 4; i++) b[i] = *(const ull*)(Bbase + i * ASTRIDE + 2 * k2);
                #pragma unroll
                for (int i = 0; i < 4; i++)
                    #pragma unroll
                    for (int j = 0; j < 8; j++) FMA2(acc[i][j], b[i], w2[j]);
            }
        }

        #pragma unroll
        for (int i = 0; i < 4; i++) {
            int row = row0 + r * 4 + i;
            if (row < n) {
                #pragma unroll
                for (int j = 0; j < 8; j++) {
                    float2 v = unpack2(acc[i][j]);
                    float s = v.x + v.y;
                    if (HASB) s += bi[j];
                    int col = c + 16 * j;
                    if (HASACC) s += accum[(size_t)row * D + col];
                    out[(size_t)row * D + col] = s;
                }
            }
        }
    }
}

// ---------------- output head: logits @ [128,10] + softmax ----------------
__global__ __launch_bounds__(256)
void out_softmax(const float* __restrict__ ht,
                 const float* __restrict__ Wout,
                 const float* __restrict__ bout,
                 float* __restrict__ out, int n) {
    __shared__ float sW[1280];
    __shared__ float sb[16];
    int tid = threadIdx.x;
    for (int i = tid; i < 1280; i += 256) sW[i] = Wout[i];
    if (tid < NOUT) sb[tid] = bout[tid];
    __syncthreads();

    int row  = (blockIdx.x * 256 + tid) >> 5;
    int lane = tid & 31;
    if (row >= n) return;
    float4 h4 = ((const float4*)(ht + (size_t)row * D))[lane];
    float h[4] = {h4.x, h4.y, h4.z, h4.w};
    float p[NOUT];
    #pragma unroll
    for (int cc = 0; cc < NOUT; cc++) {
        float s = 0.f;
        #pragma unroll
        for (int j = 0; j < 4; j++) s += h[j] * sW[(lane * 4 + j) * NOUT + cc];
        #pragma unroll
        for (int o = 16; o > 0; o >>= 1) s += __shfl_xor_sync(0xffffffffu, s, o);
        p[cc] = s + sb[cc];
    }
    if (lane == 0) {
        float m = p[0];
        #pragma unroll
        for (int cc = 1; cc < NOUT; cc++) m = fmaxf(m, p[cc]);
        float sum = 0.f;
        #pragma unroll
        for (int cc = 0; cc < NOUT; cc++) { p[cc] = expf(p[cc] - m); sum += p[cc]; }
        float isum = 1.0f / sum;
        #pragma unroll
        for (int cc = 0; cc < NOUT; cc++) out[(size_t)row * NOUT + cc] = p[cc] * isum;
    }
}

// ---------------- host orchestration ----------------
static inline void zero_buf(float* p, size_t nfloats) {
    int n4 = (int)(nfloats / 4);
    zero_f4<<<(n4 + 255) / 256, 256>>>((float4*)p, n4);
}

extern "C" void kernel_launch(void* const* d_in, const int* in_sizes, int n_in,
                              void* d_out, int out_size) {
    const float* x_c   = (const float*)d_in[0];
    const float* x_t   = (const float*)d_in[1];
    const float* x_p   = (const float*)d_in[2];
    const float* W_col = (const float*)d_in[3];
    const float* b_col = (const float*)d_in[4];
    const float* Wn    = (const float*)d_in[5];
    const float* Wr    = (const float*)d_in[6];
    const float* b_lin = (const float*)d_in[7];
    const float* W_out = (const float*)d_in[8];
    const float* b_out = (const float*)d_in[9];
    const int* em_src  = (const int*)d_in[10];
    const int* em_dst  = (const int*)d_in[11];
    const int* ei_src  = (const int*)d_in[12];
    const int* ei_dst  = (const int*)d_in[13];
    float* out = (float*)d_out;

    float *hc_base, *ht_base, *hp_base, *msg, *inv_mt, *inv_mc, *inv_it, *inv_ip, *wt_base;
    cudaGetSymbolAddress((void**)&hc_base, g_hc);
    cudaGetSymbolAddress((void**)&ht_base, g_ht);
    cudaGetSymbolAddress((void**)&hp_base, g_hp);
    cudaGetSymbolAddress((void**)&msg,     g_msg);
    cudaGetSymbolAddress((void**)&inv_mt,  g_inv_mt);
    cudaGetSymbolAddress((void**)&inv_mc,  g_inv_mc);
    cudaGetSymbolAddress((void**)&inv_it,  g_inv_it);
    cudaGetSymbolAddress((void**)&inv_ip,  g_inv_ip);
    cudaGetSymbolAddress((void**)&wt_base, g_wt);
    float* hc[2] = {hc_base, hc_base + (size_t)NC * D};
    float* ht[2] = {ht_base, ht_base + (size_t)NT * D};
    float* hp[2] = {hp_base, hp_base + (size_t)NP * D};

    cudaFuncSetAttribute(sage_gemm2<true,  false>, cudaFuncAttributeMaxDynamicSharedMemorySize, GEMM_SMEM);
    cudaFuncSetAttribute(sage_gemm2<false, true >, cudaFuncAttributeMaxDynamicSharedMemorySize, GEMM_SMEM);

    // ---- per-column embeddings ----
    embed_kernel<<<(NC * D + 255) / 256, 256>>>(x_c, W_col + 0,     b_col + 0,     hc[0], NC);
    embed_kernel<<<(NT * D + 255) / 256, 256>>>(x_t, W_col + D,     b_col + D,     ht[0], NT);
    embed_kernel<<<(NP * D + 255) / 256, 256>>>(x_p, W_col + 2 * D, b_col + 2 * D, hp[0], NP);

    // ---- combined transaction weights ----
    prep_weights<<<64, 256>>>(Wn, Wr, b_lin);

    // ---- degree inverses ----
    zero_buf(inv_mt, NT); zero_buf(inv_mc, NC); zero_buf(inv_it, NT); zero_buf(inv_ip, NP);
    count_edges<<<(EM + 255) / 256, 256>>>(em_dst, EM, inv_mt);
    count_edges<<<(EM + 255) / 256, 256>>>(em_src, EM, inv_mc);
    count_edges<<<(EI + 255) / 256, 256>>>(ei_dst, EI, inv_it);
    count_edges<<<(EI + 255) / 256, 256>>>(ei_src, EI, inv_ip);
    make_inv<<<(NT + 255) / 256, 256>>>(inv_mt, NT);
    make_inv<<<(NC + 255) / 256, 256>>>(inv_mc, NC);
    make_inv<<<(NT + 255) / 256, 256>>>(inv_it, NT);
    make_inv<<<(NP + 255) / 256, 256>>>(inv_ip, NP);

    const int GB = 148;
    const size_t WSZ = (size_t)D * D;
    int cur = 0;
    for (int l = 0; l < 2; l++) {
        int nxt = 1 - cur;
        const float* wt = wt_base + (size_t)l * WT_STRIDE;

        // transaction pass1: ht_nxt = mean0@(0.5*Wn0) + ht@(0.5*(Wr0+Wr2)) + 0.5*(b0+b2)
        zero_buf(msg, (size_t)NT * D);
        scatter_kernel<<<(EM * 32 + 255) / 256, 256>>>(hc[cur], em_src, em_dst, EM, msg);
        sage_gemm2<true, false><<<GB, 256, GEMM_SMEM>>>(
            msg, inv_mt, ht[cur], wt, wt + 32768, wt + 49152, nullptr, ht[nxt], NT);

        // transaction pass2: ht_nxt += mean2@(0.5*Wn2)
        zero_buf(msg, (size_t)NT * D);
        scatter_kernel<<<(EI * 32 + 255) / 256, 256>>>(hp[cur], ei_src, ei_dst, EI, msg);
        sage_gemm2<false, true><<<GB, 256, GEMM_SMEM>>>(
            msg, inv_it, nullptr, wt + 16384, nullptr, nullptr, ht[nxt], ht[nxt], NT);

        // customers: hc_nxt = mean@Wn1 + hc@Wr1 + b1
        zero_buf(msg, (size_t)NC * D);
        scatter_kernel<<<(EM * 32 + 255) / 256, 256>>>(ht[cur], em_dst, em_src, EM, msg);
        sage_gemm2<true, false><<<GB, 256, GEMM_SMEM>>>(
            msg, inv_mc, hc[cur], Wn + (l * 4 + 1) * WSZ, Wr + (l * 4 + 1) * WSZ,
            b_lin + (l * 4 + 1) * D, nullptr, hc[nxt], NC);

        // products: hp_nxt = mean@Wn3 + hp@Wr3 + b3
        zero_buf(msg, (size_t)NP * D);
        scatter_kernel<<<(EI * 32 + 255) / 256, 256>>>(ht[cur], ei_dst, ei_src, EI, msg);
        sage_gemm2<true, false><<<GB, 256, GEMM_SMEM>>>(
            msg, inv_ip, hp[cur], Wn + (l * 4 + 3) * WSZ, Wr + (l * 4 + 3) * WSZ,
            b_lin + (l * 4 + 3) * D, nullptr, hp[nxt], NP);

        cur = nxt;
    }

    // ---- output head ----
    out_softmax<<<(NT * 32 + 255) / 256, 256>>>(ht[cur], W_out, b_out, out, NT);
}

// round 3
// speedup vs baseline: 2.0659x; 1.6537x over previous
#include <cuda_runtime.h>

// ---------------- problem sizes ----------------
#define NC 100000
#define NT 300000
#define NP 50000
#define NF 8
#define DIMC 16
#define D 128
#define EM 300000
#define EI 600000
#define NOUT 10

typedef unsigned long long ull;

// ---------------- scratch (static device globals; allocation-free) ----------------
__device__ float g_hc[2][(size_t)NC * D];
__device__ float g_ht[2][(size_t)NT * D];
__device__ float g_hp[2][(size_t)NP * D];
__device__ float g_msg[2][(size_t)NT * D];    // msg_m / msg_i (also reused for cust/prod)
__device__ float g_srcc[(size_t)NC * D];      // hc @ Wn0h
__device__ float g_srcp[(size_t)NP * D];      // hp @ Wn2h
__device__ float g_inv_mt[NT];
__device__ float g_inv_mc[NC];
__device__ float g_inv_it[NT];
__device__ float g_inv_ip[NP];
// combined transaction weights per layer: [Wn0h | Wn2h | Wr02 | b02]
#define WT_STRIDE (3 * 16384 + 128)
__device__ float g_wt[2][WT_STRIDE];

// ---------------- small kernels ----------------
__global__ void embed_kernel(const float* __restrict__ x,
                             const float* __restrict__ W,
                             const float* __restrict__ b,
                             float* __restrict__ h, int n) {
    int idx = blockIdx.x * blockDim.x + threadIdx.x;
    if (idx >= n * D) return;
    int row = idx >> 7;
    int col = idx & 127;
    int f   = col >> 4;
    h[idx] = fmaf(x[row * NF + f], W[col], b[col]);
}

__global__ void count_edges(const int* __restrict__ dst, int E, float* __restrict__ cnt) {
    int e = blockIdx.x * blockDim.x + threadIdx.x;
    if (e < E) atomicAdd(cnt + dst[e], 1.0f);
}

__global__ void make_inv(float* __restrict__ cnt, int n) {
    int i = blockIdx.x * blockDim.x + threadIdx.x;
    if (i < n) cnt[i] = 1.0f / fmaxf(cnt[i], 1.0f);
}

__global__ void prep_weights(const float* __restrict__ Wn, const float* __restrict__ Wr,
                             const float* __restrict__ b_lin) {
    int i = blockIdx.x * blockDim.x + threadIdx.x;
    if (i >= 16384) return;
    #pragma unroll
    for (int l = 0; l < 2; l++) {
        float* base = g_wt[l];
        base[i]         = 0.5f * Wn[(l * 4 + 0) * 16384 + i];
        base[16384 + i] = 0.5f * Wn[(l * 4 + 2) * 16384 + i];
        base[32768 + i] = 0.5f * (Wr[(l * 4 + 0) * 16384 + i] + Wr[(l * 4 + 2) * 16384 + i]);
        if (i < 128)
            base[49152 + i] = 0.5f * (b_lin[(l * 4 + 0) * 128 + i] + b_lin[(l * 4 + 2) * 128 + i]);
    }
}

__device__ __forceinline__ void red_add_v4(float* addr, float4 v) {
    asm volatile("red.global.add.v4.f32 [%0], {%1,%2,%3,%4};"
                 :: "l"(addr), "f"(v.x), "f"(v.y), "f"(v.z), "f"(v.w)
                 : "memory");
}

// one warp per edge: gather 512B row, scatter-add into msg[dst]
__global__ void scatter_kernel(const float* __restrict__ hsrc,
                               const int* __restrict__ src,
                               const int* __restrict__ dst,
                               int E, float* __restrict__ msg) {
    int e    = (blockIdx.x * blockDim.x + threadIdx.x) >> 5;
    int lane = threadIdx.x & 31;
    if (e >= E) return;
    int s = src[e];
    int d = dst[e];
    float4 v = ((const float4*)(hsrc + (size_t)s * D))[lane];
    red_add_v4(msg + (size_t)d * D + lane * 4, v);
}

// ---------------- f32x2 GEMM machinery ----------------
#define ASTRIDE 132
#define FMA2(acc, a, w) asm("fma.rn.f32x2 %0, %1, %2, %0;" : "+l"(acc) : "l"(a), "l"(w))

__device__ __forceinline__ ull pack2(float lo, float hi) {
    ull p;
    asm("mov.b64 %0, {%1, %2};" : "=l"(p) : "f"(lo), "f"(hi));
    return p;
}
__device__ __forceinline__ float2 unpack2(ull p) {
    float lo, hi;
    asm("mov.b64 {%0, %1}, %2;" : "=f"(lo), "=f"(hi) : "l"(p));
    return make_float2(lo, hi);
}

// smem sizes
#define SM1 ((16384 + 64 * ASTRIDE) * 4)                 // 1-matrix kernels: 99,328 B (2 CTA/SM)
#define SM2 ((16384 + 16384 + 64 * ASTRIDE * 2) * 4)     // 2-matrix kernel: 198,656 B (1 CTA/SM)

// ---- transform: out = A @ W  (no inv, no bias) ----
__global__ __launch_bounds__(256)
void xform_gemm(const float* __restrict__ A, const float* __restrict__ W,
                float* __restrict__ out, int n) {
    extern __shared__ float sm[];
    ull*   Wp  = (ull*)sm;                   // 64 k2 x 128 col
    float* A_s = sm + 16384;

    const int tid = threadIdx.x;
    for (int i = tid; i < 8192; i += 256) {
        int k2 = i >> 7, col = i & 127;
        Wp[i] = pack2(W[(2 * k2) * 128 + col], W[(2 * k2 + 1) * 128 + col]);
    }
    const int c = tid & 15;
    const int r = tid >> 4;

    const int ntiles = (n + 63) >> 6;
    for (int t = blockIdx.x; t < ntiles; t += gridDim.x) {
        const int row0 = t << 6;
        __syncthreads();
        for (int i = tid; i < 2048; i += 256) {
            int rr = i >> 5, col4 = i & 31;
            int row = row0 + rr;
            float4 a = (row < n) ? ((const float4*)A)[(size_t)row * 32 + col4]
                                 : make_float4(0.f, 0.f, 0.f, 0.f);
            ((float4*)(A_s + rr * ASTRIDE))[col4] = a;
        }
        __syncthreads();

        ull acc[4][8];
        #pragma unroll
        for (int i = 0; i < 4; i++)
            #pragma unroll
            for (int j = 0; j < 8; j++) acc[i][j] = 0ull;

        const float* Abase = A_s + (r * 4) * ASTRIDE;
        #pragma unroll 2
        for (int k2 = 0; k2 < 64; k2++) {
            ull w[8], a[4];
            #pragma unroll
            for (int j = 0; j < 8; j++) w[j] = Wp[k2 * 128 + c + 16 * j];
            #pragma unroll
            for (int i = 0; i < 4; i++) a[i] = *(const ull*)(Abase + i * ASTRIDE + 2 * k2);
            #pragma unroll
            for (int i = 0; i < 4; i++)
                #pragma unroll
                for (int j = 0; j < 8; j++) FMA2(acc[i][j], a[i], w[j]);
        }
        #pragma unroll
        for (int i = 0; i < 4; i++) {
            int row = row0 + r * 4 + i;
            if (row < n) {
                #pragma unroll
                for (int j = 0; j < 8; j++) {
                    float2 v = unpack2(acc[i][j]);
                    out[(size_t)row * D + c + 16 * j] = v.x + v.y;
                }
            }
        }
    }
}

// ---- transaction root: out = hdst@W + bias + inv1*msg1 + inv2*msg2 ----
__global__ __launch_bounds__(256)
void root_gemm(const float* __restrict__ hdst, const float* __restrict__ W,
               const float* __restrict__ bias,
               const float* __restrict__ msg1, const float* __restrict__ inv1,
               const float* __restrict__ msg2, const float* __restrict__ inv2,
               float* __restrict__ out, int n) {
    extern __shared__ float sm[];
    ull*   Wp  = (ull*)sm;
    float* A_s = sm + 16384;

    const int tid = threadIdx.x;
    for (int i = tid; i < 8192; i += 256) {
        int k2 = i >> 7, col = i & 127;
        Wp[i] = pack2(W[(2 * k2) * 128 + col], W[(2 * k2 + 1) * 128 + col]);
    }
    const int c = tid & 15;
    const int r = tid >> 4;
    float bi[8];
    #pragma unroll
    for (int j = 0; j < 8; j++) bi[j] = bias[c + 16 * j];

    const int ntiles = (n + 63) >> 6;
    for (int t = blockIdx.x; t < ntiles; t += gridDim.x) {
        const int row0 = t << 6;
        __syncthreads();
        for (int i = tid; i < 2048; i += 256) {
            int rr = i >> 5, col4 = i & 31;
            int row = row0 + rr;
            float4 a = (row < n) ? ((const float4*)hdst)[(size_t)row * 32 + col4]
                                 : make_float4(0.f, 0.f, 0.f, 0.f);
            ((float4*)(A_s + rr * ASTRIDE))[col4] = a;
        }
        __syncthreads();

        ull acc[4][8];
        #pragma unroll
        for (int i = 0; i < 4; i++)
            #pragma unroll
            for (int j = 0; j < 8; j++) acc[i][j] = 0ull;

        const float* Abase = A_s + (r * 4) * ASTRIDE;
        #pragma unroll 2
        for (int k2 = 0; k2 < 64; k2++) {
            ull w[8], a[4];
            #pragma unroll
            for (int j = 0; j < 8; j++) w[j] = Wp[k2 * 128 + c + 16 * j];
            #pragma unroll
            for (int i = 0; i < 4; i++) a[i] = *(const ull*)(Abase + i * ASTRIDE + 2 * k2);
            #pragma unroll
            for (int i = 0; i < 4; i++)
                #pragma unroll
                for (int j = 0; j < 8; j++) FMA2(acc[i][j], a[i], w[j]);
        }
        #pragma unroll
        for (int i = 0; i < 4; i++) {
            int row = row0 + r * 4 + i;
            if (row < n) {
                float i1 = inv1[row];
                float i2 = inv2[row];
                #pragma unroll
                for (int j = 0; j < 8; j++) {
                    int col = c + 16 * j;
                    float2 v = unpack2(acc[i][j]);
                    float s = v.x + v.y + bi[j];
                    s += i1 * msg1[(size_t)row * D + col];
                    s += i2 * msg2[(size_t)row * D + col];
                    out[(size_t)row * D + col] = s;
                }
            }
        }
    }
}

// ---- two-matrix SAGE: out = (msg*inv)@W1 + hdst@W2 + bias ----
__global__ __launch_bounds__(256)
void sage_gemm2(const float* __restrict__ msg, const float* __restrict__ inv,
                const float* __restrict__ hdst,
                const float* __restrict__ W1, const float* __restrict__ W2,
                const float* __restrict__ bias,
                float* __restrict__ out, int n) {
    extern __shared__ float sm[];
    ull*   Wp1 = (ull*)sm;
    ull*   Wp2 = (ull*)(sm + 16384);
    float* A_s = sm + 32768;
    float* B_s = A_s + 64 * ASTRIDE;

    const int tid = threadIdx.x;
    for (int i = tid; i < 8192; i += 256) {
        int k2 = i >> 7, col = i & 127;
        Wp1[i] = pack2(W1[(2 * k2) * 128 + col], W1[(2 * k2 + 1) * 128 + col]);
        Wp2[i] = pack2(W2[(2 * k2) * 128 + col], W2[(2 * k2 + 1) * 128 + col]);
    }
    const int c = tid & 15;
    const int r = tid >> 4;
    float bi[8];
    #pragma unroll
    for (int j = 0; j < 8; j++) bi[j] = bias[c + 16 * j];

    const int ntiles = (n + 63) >> 6;
    for (int t = blockIdx.x; t < ntiles; t += gridDim.x) {
        const int row0 = t << 6;
        __syncthreads();
        for (int i = tid; i < 2048; i += 256) {
            int rr = i >> 5, col4 = i & 31;
            int row = row0 + rr;
            float4 a, b;
            if (row < n) {
                a = ((const float4*)msg)[(size_t)row * 32 + col4];
                float iv = inv[row];
                a.x *= iv; a.y *= iv; a.z *= iv; a.w *= iv;
                b = ((const float4*)hdst)[(size_t)row * 32 + col4];
            } else {
                a = make_float4(0.f, 0.f, 0.f, 0.f);
                b = a;
            }
            ((float4*)(A_s + rr * ASTRIDE))[col4] = a;
            ((float4*)(B_s + rr * ASTRIDE))[col4] = b;
        }
        __syncthreads();

        ull acc[4][8];
        #pragma unroll
        for (int i = 0; i < 4; i++)
            #pragma unroll
            for (int j = 0; j < 8; j++) acc[i][j] = 0ull;

        const float* Abase = A_s + (r * 4) * ASTRIDE;
        const float* Bbase = B_s + (r * 4) * ASTRIDE;
        #pragma unroll 2
        for (int k2 = 0; k2 < 64; k2++) {
            ull w1[8], a[4];
            #pragma unroll
            for (int j = 0; j < 8; j++) w1[j] = Wp1[k2 * 128 + c + 16 * j];
            #pragma unroll
            for (int i = 0; i < 4; i++) a[i] = *(const ull*)(Abase + i * ASTRIDE + 2 * k2);
            #pragma unroll
            for (int i = 0; i < 4; i++)
                #pragma unroll
                for (int j = 0; j < 8; j++) FMA2(acc[i][j], a[i], w1[j]);
            ull w2[8], b[4];
            #pragma unroll
            for (int j = 0; j < 8; j++) w2[j] = Wp2[k2 * 128 + c + 16 * j];
            #pragma unroll
            for (int i = 0; i < 4; i++) b[i] = *(const ull*)(Bbase + i * ASTRIDE + 2 * k2);
            #pragma unroll
            for (int i = 0; i < 4; i++)
                #pragma unroll
                for (int j = 0; j < 8; j++) FMA2(acc[i][j], b[i], w2[j]);
        }
        #pragma unroll
        for (int i = 0; i < 4; i++) {
            int row = row0 + r * 4 + i;
            if (row < n) {
                #pragma unroll
                for (int j = 0; j < 8; j++) {
                    float2 v = unpack2(acc[i][j]);
                    out[(size_t)row * D + c + 16 * j] = v.x + v.y + bi[j];
                }
            }
        }
    }
}

// ---------------- output head: logits @ [128,10] + softmax ----------------
__global__ __launch_bounds__(256)
void out_softmax(const float* __restrict__ ht,
                 const float* __restrict__ Wout,
                 const float* __restrict__ bout,
                 float* __restrict__ out, int n) {
    __shared__ float sW[1280];
    __shared__ float sb[16];
    int tid = threadIdx.x;
    for (int i = tid; i < 1280; i += 256) sW[i] = Wout[i];
    if (tid < NOUT) sb[tid] = bout[tid];
    __syncthreads();

    int row  = (blockIdx.x * 256 + tid) >> 5;
    int lane = tid & 31;
    if (row >= n) return;
    float4 h4 = ((const float4*)(ht + (size_t)row * D))[lane];
    float h[4] = {h4.x, h4.y, h4.z, h4.w};
    float p[NOUT];
    #pragma unroll
    for (int cc = 0; cc < NOUT; cc++) {
        float s = 0.f;
        #pragma unroll
        for (int j = 0; j < 4; j++) s += h[j] * sW[(lane * 4 + j) * NOUT + cc];
        #pragma unroll
        for (int o = 16; o > 0; o >>= 1) s += __shfl_xor_sync(0xffffffffu, s, o);
        p[cc] = s + sb[cc];
    }
    if (lane == 0) {
        float m = p[0];
        #pragma unroll
        for (int cc = 1; cc < NOUT; cc++) m = fmaxf(m, p[cc]);
        float sum = 0.f;
        #pragma unroll
        for (int cc = 0; cc < NOUT; cc++) { p[cc] = expf(p[cc] - m); sum += p[cc]; }
        float isum = 1.0f / sum;
        #pragma unroll
        for (int cc = 0; cc < NOUT; cc++) out[(size_t)row * NOUT + cc] = p[cc] * isum;
    }
}

// ---------------- host orchestration ----------------
extern "C" void kernel_launch(void* const* d_in, const int* in_sizes, int n_in,
                              void* d_out, int out_size) {
    const float* x_c   = (const float*)d_in[0];
    const float* x_t   = (const float*)d_in[1];
    const float* x_p   = (const float*)d_in[2];
    const float* W_col = (const float*)d_in[3];
    const float* b_col = (const float*)d_in[4];
    const float* Wn    = (const float*)d_in[5];
    const float* Wr    = (const float*)d_in[6];
    const float* b_lin = (const float*)d_in[7];
    const float* W_out = (const float*)d_in[8];
    const float* b_out = (const float*)d_in[9];
    const int* em_src  = (const int*)d_in[10];
    const int* em_dst  = (const int*)d_in[11];
    const int* ei_src  = (const int*)d_in[12];
    const int* ei_dst  = (const int*)d_in[13];
    float* out = (float*)d_out;

    float *hc_base, *ht_base, *hp_base, *msg_base, *srcc, *srcp;
    float *inv_mt, *inv_mc, *inv_it, *inv_ip, *wt_base;
    cudaGetSymbolAddress((void**)&hc_base,  g_hc);
    cudaGetSymbolAddress((void**)&ht_base,  g_ht);
    cudaGetSymbolAddress((void**)&hp_base,  g_hp);
    cudaGetSymbolAddress((void**)&msg_base, g_msg);
    cudaGetSymbolAddress((void**)&srcc,     g_srcc);
    cudaGetSymbolAddress((void**)&srcp,     g_srcp);
    cudaGetSymbolAddress((void**)&inv_mt,   g_inv_mt);
    cudaGetSymbolAddress((void**)&inv_mc,   g_inv_mc);
    cudaGetSymbolAddress((void**)&inv_it,   g_inv_it);
    cudaGetSymbolAddress((void**)&inv_ip,   g_inv_ip);
    cudaGetSymbolAddress((void**)&wt_base,  g_wt);
    float* hc[2] = {hc_base, hc_base + (size_t)NC * D};
    float* ht[2] = {ht_base, ht_base + (size_t)NT * D};
    float* hp[2] = {hp_base, hp_base + (size_t)NP * D};
    float* msg_m = msg_base;
    float* msg_i = msg_base + (size_t)NT * D;

    cudaFuncSetAttribute(xform_gemm, cudaFuncAttributeMaxDynamicSharedMemorySize, SM1);
    cudaFuncSetAttribute(root_gemm,  cudaFuncAttributeMaxDynamicSharedMemorySize, SM1);
    cudaFuncSetAttribute(sage_gemm2, cudaFuncAttributeMaxDynamicSharedMemorySize, SM2);

    // ---- embeddings ----
    embed_kernel<<<(NC * D + 255) / 256, 256>>>(x_c, W_col + 0,     b_col + 0,     hc[0], NC);
    embed_kernel<<<(NT * D + 255) / 256, 256>>>(x_t, W_col + D,     b_col + D,     ht[0], NT);
    embed_kernel<<<(NP * D + 255) / 256, 256>>>(x_p, W_col + 2 * D, b_col + 2 * D, hp[0], NP);

    // ---- combined transaction weights ----
    prep_weights<<<64, 256>>>(Wn, Wr, b_lin);

    // ---- degree inverses ----
    cudaMemsetAsync(inv_mt, 0, NT * sizeof(float));
    cudaMemsetAsync(inv_mc, 0, NC * sizeof(float));
    cudaMemsetAsync(inv_it, 0, NT * sizeof(float));
    cudaMemsetAsync(inv_ip, 0, NP * sizeof(float));
    count_edges<<<(EM + 255) / 256, 256>>>(em_dst, EM, inv_mt);
    count_edges<<<(EM + 255) / 256, 256>>>(em_src, EM, inv_mc);
    count_edges<<<(EI + 255) / 256, 256>>>(ei_dst, EI, inv_it);
    count_edges<<<(EI + 255) / 256, 256>>>(ei_src, EI, inv_ip);
    make_inv<<<(NT + 255) / 256, 256>>>(inv_mt, NT);
    make_inv<<<(NC + 255) / 256, 256>>>(inv_mc, NC);
    make_inv<<<(NT + 255) / 256, 256>>>(inv_it, NT);
    make_inv<<<(NP + 255) / 256, 256>>>(inv_ip, NP);

    const int GB1 = 296;   // 1-matrix kernels: 2 CTA/SM
    const int GB2 = 148;   // 2-matrix kernel: 1 CTA/SM
    const size_t WSZ = (size_t)D * D;

    for (int l = 0; l < 2; l++) {
        int cur = l, nxt = 1 - l;   // ping-pong (layer0: 0->1, layer1: 1->0)
        const float* wt = wt_base + (size_t)l * WT_STRIDE;

        // 1) transform sources for transaction update
        xform_gemm<<<GB1, 256, SM1>>>(hc[cur], wt,         srcc, NC);
        xform_gemm<<<GB1, 256, SM1>>>(hp[cur], wt + 16384, srcp, NP);

        // 2) scatter transformed sources into msg_m / msg_i
        cudaMemsetAsync(msg_m, 0, (size_t)NT * D * sizeof(float));
        cudaMemsetAsync(msg_i, 0, (size_t)NT * D * sizeof(float));
        scatter_kernel<<<(EM * 32 + 255) / 256, 256>>>(srcc, em_src, em_dst, EM, msg_m);
        scatter_kernel<<<(EI * 32 + 255) / 256, 256>>>(srcp, ei_src, ei_dst, EI, msg_i);

        // 3) transaction root + combine:
        //    ht_nxt = ht@Wr02 + b02 + inv_mt*msg_m + inv_it*msg_i
        root_gemm<<<GB1, 256, SM1>>>(ht[cur], wt + 32768, wt + 49152,
                                     msg_m, inv_mt, msg_i, inv_it, ht[nxt], NT);

        if (l == 0) {
            // 4) customers (layer 1 only; layer-2 hc is dead code)
            cudaMemsetAsync(msg_m, 0, (size_t)NC * D * sizeof(float));
            scatter_kernel<<<(EM * 32 + 255) / 256, 256>>>(ht[cur], em_dst, em_src, EM, msg_m);
            sage_gemm2<<<GB2, 256, SM2>>>(msg_m, inv_mc, hc[cur],
                                          Wn + 1 * WSZ, Wr + 1 * WSZ, b_lin + 1 * D,
                                          hc[nxt], NC);
            // 5) products (layer 1 only)
            cudaMemsetAsync(msg_i, 0, (size_t)NP * D * sizeof(float));
            scatter_kernel<<<(EI * 32 + 255) / 256, 256>>>(ht[cur], ei_dst, ei_src, EI, msg_i);
            sage_gemm2<<<GB2, 256, SM2>>>(msg_i, inv_ip, hp[cur],
                                          Wn + 3 * WSZ, Wr + 3 * WSZ, b_lin + 3 * D,
                                          hp[nxt], NP);
        }
    }

    // ---- output head (final ht is ht[0] after 2 ping-pongs) ----
    out_softmax<<<(NT * 32 + 255) / 256, 256>>>(ht[0], W_out, b_out, out, NT);
}

// round 4
// speedup vs baseline: 2.8924x; 1.4001x over previous
#include <cuda_runtime.h>

// ---------------- problem sizes ----------------
#define NC 100000
#define NT 300000
#define NP 50000
#define NF 8
#define D 128
#define EM 300000
#define EI 600000
#define NOUT 10

typedef unsigned long long ull;

// ---------------- scratch ----------------
__device__ float g_ht1[(size_t)NT * D];
__device__ float g_ht2[(size_t)NT * D];
__device__ float g_hc1[(size_t)NC * D];
__device__ float g_hp1[(size_t)NP * D];
__device__ float g_msgm[(size_t)NT * D];
__device__ float g_msgi[(size_t)NT * D];
__device__ float g_msgc[(size_t)NC * D];
__device__ float g_msgp[(size_t)NP * D];
__device__ float g_srcc[(size_t)NC * D];
__device__ float g_srcp[(size_t)NP * D];
__device__ float g_inv_mt[NT];
__device__ float g_inv_mc[NC];
__device__ float g_inv_it[NT];
__device__ float g_inv_ip[NP];
// 7 small layer-1 matrices [8,128] + bias rows [128]
__device__ float g_sw[7][8 * D];
__device__ float g_sb[7][D];
// layer-2 combined transaction weights: [Wn0h | Wn2h | Wr02 | b02]
#define WT_STRIDE (3 * 16384 + 128)
__device__ float g_wt[WT_STRIDE];

// ---------------- degree kernels ----------------
__global__ void count_edges(const int* __restrict__ dst, int E, float* __restrict__ cnt) {
    int e = blockIdx.x * blockDim.x + threadIdx.x;
    if (e < E) atomicAdd(cnt + dst[e], 1.0f);
}
__global__ void make_inv(float* __restrict__ cnt, int n) {
    int i = blockIdx.x * blockDim.x + threadIdx.x;
    if (i < n) cnt[i] = 1.0f / fmaxf(cnt[i], 1.0f);
}

// ---------------- weight prep ----------------
// layer-2 combined: Wn0h=0.5*Wn[1,0], Wn2h=0.5*Wn[1,2], Wr02=0.5*(Wr[1,0]+Wr[1,2]), b02
__global__ void prep_weights2(const float* __restrict__ Wn, const float* __restrict__ Wr,
                              const float* __restrict__ b_lin) {
    int i = blockIdx.x * blockDim.x + threadIdx.x;
    if (i >= 16384) return;
    g_wt[i]         = 0.5f * Wn[(4 + 0) * 16384 + i];
    g_wt[16384 + i] = 0.5f * Wn[(4 + 2) * 16384 + i];
    g_wt[32768 + i] = 0.5f * (Wr[(4 + 0) * 16384 + i] + Wr[(4 + 2) * 16384 + i]);
    if (i < 128)
        g_wt[49152 + i] = 0.5f * (b_lin[(4 + 0) * 128 + i] + b_lin[(4 + 2) * 128 + i]);
}

// layer-1 small mats: g_sw[m][f,col] = sum_d W_col[X,f,d]*M[f*16+d,col]
// g_sb[m][col] = sum_{f,d} b_col[X,f,d]*M[f*16+d,col] (+ extra bias)
// m: 0=src_c(0.5*Wn00,X=0) 1=src_p(0.5*Wn02,X=2) 2=root_t(0.5*(Wr00+Wr02),X=1,+0.5*(b00+b02))
//    3=src_t1(Wn01,X=1) 4=src_t3(Wn03,X=1) 5=root_c(Wr01,X=0,+b01) 6=root_p(Wr03,X=2,+b03)
__global__ void prep_small(const float* __restrict__ W_col, const float* __restrict__ b_col,
                           const float* __restrict__ Wn, const float* __restrict__ Wr,
                           const float* __restrict__ b_lin) {
    int m   = blockIdx.x;
    int col = threadIdx.x;
    const float* M1 = nullptr; const float* M2 = nullptr;
    float scale = 1.0f; int X = 0;
    const float* bext = nullptr; float bext_scale = 1.0f;
    const float* bext2 = nullptr;
    switch (m) {
        case 0: X = 0; M1 = Wn + 0 * 16384; scale = 0.5f; break;
        case 1: X = 2; M1 = Wn + 2 * 16384; scale = 0.5f; break;
        case 2: X = 1; M1 = Wr + 0 * 16384; M2 = Wr + 2 * 16384; scale = 0.5f;
                bext = b_lin + 0 * 128; bext2 = b_lin + 2 * 128; bext_scale = 0.5f; break;
        case 3: X = 1; M1 = Wn + 1 * 16384; break;
        case 4: X = 1; M1 = Wn + 3 * 16384; break;
        case 5: X = 0; M1 = Wr + 1 * 16384; bext = b_lin + 1 * 128; break;
        case 6: X = 2; M1 = Wr + 3 * 16384; bext = b_lin + 3 * 128; break;
    }
    float bias = 0.f;
    for (int f = 0; f < NF; f++) {
        float acc = 0.f;
        for (int d = 0; d < 16; d++) {
            int k = f * 16 + d;
            float mk = M1[k * 128 + col];
            if (M2) mk += M2[k * 128 + col];
            mk *= scale;
            acc  += W_col[X * 128 + k] * mk;
            bias += b_col[X * 128 + k] * mk;
        }
        g_sw[m][f * 128 + col] = acc;
    }
    if (bext)  bias += bext_scale * bext[col];
    if (bext2) bias += bext_scale * bext2[col];
    g_sb[m][col] = bias;
}

// ---------------- scatter (fused K=8 transform) ----------------
__device__ __forceinline__ void red_add_v4(float* addr, float4 v) {
    asm volatile("red.global.add.v4.f32 [%0], {%1,%2,%3,%4};"
                 :: "l"(addr), "f"(v.x), "f"(v.y), "f"(v.z), "f"(v.w)
                 : "memory");
}

// one warp per edge: v = x[src]@Ws + bs (K=8), scatter-add into msg[dst]
__global__ __launch_bounds__(256)
void scatter8(const float* __restrict__ x, int midx,
              const int* __restrict__ src, const int* __restrict__ dst,
              int E, float* __restrict__ msg) {
    __shared__ float4 sW[256];
    __shared__ float4 sb[32];
    int tid = threadIdx.x;
    sW[tid] = ((const float4*)g_sw[midx])[tid];
    if (tid < 32) sb[tid] = ((const float4*)g_sb[midx])[tid];
    __syncthreads();

    int e    = (blockIdx.x * 256 + tid) >> 5;
    int lane = tid & 31;
    if (e >= E) return;
    int s = src[e];
    int d = dst[e];
    const float4* xr = (const float4*)(x + (size_t)s * NF);
    float4 x0 = xr[0], x1 = xr[1];
    float xf[8] = {x0.x, x0.y, x0.z, x0.w, x1.x, x1.y, x1.z, x1.w};
    float4 v = sb[lane];
    #pragma unroll
    for (int f = 0; f < 8; f++) {
        float4 w = sW[f * 32 + lane];
        v.x = fmaf(xf[f], w.x, v.x);
        v.y = fmaf(xf[f], w.y, v.y);
        v.z = fmaf(xf[f], w.z, v.z);
        v.w = fmaf(xf[f], w.w, v.w);
    }
    red_add_v4(msg + (size_t)d * D + lane * 4, v);
}

// full-width scatter (layer-2): gather 512B row, scatter-add
__global__ __launch_bounds__(256)
void scatter_kernel(const float* __restrict__ hsrc,
                    const int* __restrict__ src, const int* __restrict__ dst,
                    int E, float* __restrict__ msg) {
    int e    = (blockIdx.x * 256 + threadIdx.x) >> 5;
    int lane = threadIdx.x & 31;
    if (e >= E) return;
    int s = src[e];
    int d = dst[e];
    float4 v = ((const float4*)(hsrc + (size_t)s * D))[lane];
    red_add_v4(msg + (size_t)d * D + lane * 4, v);
}

// ---------------- layer-1 combine: out = x@Ws + bs + inv1*msg1 [+ inv2*msg2] ----------------
template <bool TWO>
__global__ __launch_bounds__(256)
void combine8(const float* __restrict__ x, int midx,
              const float* __restrict__ msg1, const float* __restrict__ inv1,
              const float* __restrict__ msg2, const float* __restrict__ inv2,
              float* __restrict__ out, int n) {
    __shared__ float4 sW[256];
    __shared__ float4 sb[32];
    int tid = threadIdx.x;
    sW[tid] = ((const float4*)g_sw[midx])[tid];
    if (tid < 32) sb[tid] = ((const float4*)g_sb[midx])[tid];
    __syncthreads();

    int row  = (blockIdx.x * 256 + tid) >> 5;
    int lane = tid & 31;
    if (row >= n) return;
    const float4* xr = (const float4*)(x + (size_t)row * NF);
    float4 x0 = xr[0], x1 = xr[1];
    float xf[8] = {x0.x, x0.y, x0.z, x0.w, x1.x, x1.y, x1.z, x1.w};
    float4 v = sb[lane];
    #pragma unroll
    for (int f = 0; f < 8; f++) {
        float4 w = sW[f * 32 + lane];
        v.x = fmaf(xf[f], w.x, v.x);
        v.y = fmaf(xf[f], w.y, v.y);
        v.z = fmaf(xf[f], w.z, v.z);
        v.w = fmaf(xf[f], w.w, v.w);
    }
    float i1 = inv1[row];
    float4 m1 = ((const float4*)msg1)[(size_t)row * 32 + lane];
    v.x = fmaf(i1, m1.x, v.x);
    v.y = fmaf(i1, m1.y, v.y);
    v.z = fmaf(i1, m1.z, v.z);
    v.w = fmaf(i1, m1.w, v.w);
    if (TWO) {
        float i2 = inv2[row];
        float4 m2 = ((const float4*)msg2)[(size_t)row * 32 + lane];
        v.x = fmaf(i2, m2.x, v.x);
        v.y = fmaf(i2, m2.y, v.y);
        v.z = fmaf(i2, m2.z, v.z);
        v.w = fmaf(i2, m2.w, v.w);
    }
    ((float4*)out)[(size_t)row * 32 + lane] = v;
}

// ---------------- f32x2 GEMM machinery (layer-2, K=128) ----------------
#define ASTRIDE 132
#define FMA2(acc, a, w) asm("fma.rn.f32x2 %0, %1, %2, %0;" : "+l"(acc) : "l"(a), "l"(w))

__device__ __forceinline__ ull pack2(float lo, float hi) {
    ull p;
    asm("mov.b64 %0, {%1, %2};" : "=l"(p) : "f"(lo), "f"(hi));
    return p;
}
__device__ __forceinline__ float2 unpack2(ull p) {
    float lo, hi;
    asm("mov.b64 {%0, %1}, %2;" : "=f"(lo), "=f"(hi) : "l"(p));
    return make_float2(lo, hi);
}

#define SM1 ((16384 + 64 * ASTRIDE) * 4)   // 99,328 B -> 2 CTA/SM

// out = A @ W
__global__ __launch_bounds__(256)
void xform_gemm(const float* __restrict__ A, const float* __restrict__ W,
                float* __restrict__ out, int n) {
    extern __shared__ float sm[];
    ull*   Wp  = (ull*)sm;
    float* A_s = sm + 16384;
    const int tid = threadIdx.x;
    for (int i = tid; i < 8192; i += 256) {
        int k2 = i >> 7, col = i & 127;
        Wp[i] = pack2(W[(2 * k2) * 128 + col], W[(2 * k2 + 1) * 128 + col]);
    }
    const int c = tid & 15;
    const int r = tid >> 4;
    const int ntiles = (n + 63) >> 6;
    for (int t = blockIdx.x; t < ntiles; t += gridDim.x) {
        const int row0 = t << 6;
        __syncthreads();
        for (int i = tid; i < 2048; i += 256) {
            int rr = i >> 5, col4 = i & 31;
            int row = row0 + rr;
            float4 a = (row < n) ? ((const float4*)A)[(size_t)row * 32 + col4]
                                 : make_float4(0.f, 0.f, 0.f, 0.f);
            ((float4*)(A_s + rr * ASTRIDE))[col4] = a;
        }
        __syncthreads();
        ull acc[4][8];
        #pragma unroll
        for (int i = 0; i < 4; i++)
            #pragma unroll
            for (int j = 0; j < 8; j++) acc[i][j] = 0ull;
        const float* Abase = A_s + (r * 4) * ASTRIDE;
        #pragma unroll 2
        for (int k2 = 0; k2 < 64; k2++) {
            ull w[8], a[4];
            #pragma unroll
            for (int j = 0; j < 8; j++) w[j] = Wp[k2 * 128 + c + 16 * j];
            #pragma unroll
            for (int i = 0; i < 4; i++) a[i] = *(const ull*)(Abase + i * ASTRIDE + 2 * k2);
            #pragma unroll
            for (int i = 0; i < 4; i++)
                #pragma unroll
                for (int j = 0; j < 8; j++) FMA2(acc[i][j], a[i], w[j]);
        }
        #pragma unroll
        for (int i = 0; i < 4; i++) {
            int row = row0 + r * 4 + i;
            if (row < n) {
                #pragma unroll
                for (int j = 0; j < 8; j++) {
                    float2 v = unpack2(acc[i][j]);
                    out[(size_t)row * D + c + 16 * j] = v.x + v.y;
                }
            }
        }
    }
}

// out = hdst@W + bias + inv1*msg1 + inv2*msg2
__global__ __launch_bounds__(256)
void root_gemm(const float* __restrict__ hdst, const float* __restrict__ W,
               const float* __restrict__ bias,
               const float* __restrict__ msg1, const float* __restrict__ inv1,
               const float* __restrict__ msg2, const float* __restrict__ inv2,
               float* __restrict__ out, int n) {
    extern __shared__ float sm[];
    ull*   Wp  = (ull*)sm;
    float* A_s = sm + 16384;
    const int tid = threadIdx.x;
    for (int i = tid; i < 8192; i += 256) {
        int k2 = i >> 7, col = i & 127;
        Wp[i] = pack2(W[(2 * k2) * 128 + col], W[(2 * k2 + 1) * 128 + col]);
    }
    const int c = tid & 15;
    const int r = tid >> 4;
    float bi[8];
    #pragma unroll
    for (int j = 0; j < 8; j++) bi[j] = bias[c + 16 * j];
    const int ntiles = (n + 63) >> 6;
    for (int t = blockIdx.x; t < ntiles; t += gridDim.x) {
        const int row0 = t << 6;
        __syncthreads();
        for (int i = tid; i < 2048; i += 256) {
            int rr = i >> 5, col4 = i & 31;
            int row = row0 + rr;
            float4 a = (row < n) ? ((const float4*)hdst)[(size_t)row * 32 + col4]
                                 : make_float4(0.f, 0.f, 0.f, 0.f);
            ((float4*)(A_s + rr * ASTRIDE))[col4] = a;
        }
        __syncthreads();
        ull acc[4][8];
        #pragma unroll
        for (int i = 0; i < 4; i++)
            #pragma unroll
            for (int j = 0; j < 8; j++) acc[i][j] = 0ull;
        const float* Abase = A_s + (r * 4) * ASTRIDE;
        #pragma unroll 2
        for (int k2 = 0; k2 < 64; k2++) {
            ull w[8], a[4];
            #pragma unroll
            for (int j = 0; j < 8; j++) w[j] = Wp[k2 * 128 + c + 16 * j];
            #pragma unroll
            for (int i = 0; i < 4; i++) a[i] = *(const ull*)(Abase + i * ASTRIDE + 2 * k2);
            #pragma unroll
            for (int i = 0; i < 4; i++)
                #pragma unroll
                for (int j = 0; j < 8; j++) FMA2(acc[i][j], a[i], w[j]);
        }
        #pragma unroll
        for (int i = 0; i < 4; i++) {
            int row = row0 + r * 4 + i;
            if (row < n) {
                float i1 = inv1[row];
                float i2 = inv2[row];
                #pragma unroll
                for (int j = 0; j < 8; j++) {
                    int col = c + 16 * j;
                    float2 v = unpack2(acc[i][j]);
                    float s = v.x + v.y + bi[j];
                    s += i1 * msg1[(size_t)row * D + col];
                    s += i2 * msg2[(size_t)row * D + col];
                    out[(size_t)row * D + col] = s;
                }
            }
        }
    }
}

// ---------------- output head ----------------
__global__ __launch_bounds__(256)
void out_softmax(const float* __restrict__ ht,
                 const float* __restrict__ Wout,
                 const float* __restrict__ bout,
                 float* __restrict__ out, int n) {
    __shared__ float sW[1280];
    __shared__ float sb[16];
    int tid = threadIdx.x;
    for (int i = tid; i < 1280; i += 256) sW[i] = Wout[i];
    if (tid < NOUT) sb[tid] = bout[tid];
    __syncthreads();

    int row  = (blockIdx.x * 256 + tid) >> 5;
    int lane = tid & 31;
    if (row >= n) return;
    float4 h4 = ((const float4*)(ht + (size_t)row * D))[lane];
    float h[4] = {h4.x, h4.y, h4.z, h4.w};
    float p[NOUT];
    #pragma unroll
    for (int cc = 0; cc < NOUT; cc++) {
        float s = 0.f;
        #pragma unroll
        for (int j = 0; j < 4; j++) s += h[j] * sW[(lane * 4 + j) * NOUT + cc];
        #pragma unroll
        for (int o = 16; o > 0; o >>= 1) s += __shfl_xor_sync(0xffffffffu, s, o);
        p[cc] = s + sb[cc];
    }
    if (lane == 0) {
        float m = p[0];
        #pragma unroll
        for (int cc = 1; cc < NOUT; cc++) m = fmaxf(m, p[cc]);
        float sum = 0.f;
        #pragma unroll
        for (int cc = 0; cc < NOUT; cc++) { p[cc] = expf(p[cc] - m); sum += p[cc]; }
        float isum = 1.0f / sum;
        #pragma unroll
        for (int cc = 0; cc < NOUT; cc++) out[(size_t)row * NOUT + cc] = p[cc] * isum;
    }
}

// ---------------- host orchestration ----------------
extern "C" void kernel_launch(void* const* d_in, const int* in_sizes, int n_in,
                              void* d_out, int out_size) {
    const float* x_c   = (const float*)d_in[0];
    const float* x_t   = (const float*)d_in[1];
    const float* x_p   = (const float*)d_in[2];
    const float* W_col = (const float*)d_in[3];
    const float* b_col = (const float*)d_in[4];
    const float* Wn    = (const float*)d_in[5];
    const float* Wr    = (const float*)d_in[6];
    const float* b_lin = (const float*)d_in[7];
    const float* W_out = (const float*)d_in[8];
    const float* b_out = (const float*)d_in[9];
    const int* em_src  = (const int*)d_in[10];
    const int* em_dst  = (const int*)d_in[11];
    const int* ei_src  = (const int*)d_in[12];
    const int* ei_dst  = (const int*)d_in[13];
    float* out = (float*)d_out;

    float *ht1, *ht2, *hc1, *hp1, *msgm, *msgi, *msgc, *msgp, *srcc, *srcp;
    float *inv_mt, *inv_mc, *inv_it, *inv_ip, *wt;
    cudaGetSymbolAddress((void**)&ht1,    g_ht1);
    cudaGetSymbolAddress((void**)&ht2,    g_ht2);
    cudaGetSymbolAddress((void**)&hc1,    g_hc1);
    cudaGetSymbolAddress((void**)&hp1,    g_hp1);
    cudaGetSymbolAddress((void**)&msgm,   g_msgm);
    cudaGetSymbolAddress((void**)&msgi,   g_msgi);
    cudaGetSymbolAddress((void**)&msgc,   g_msgc);
    cudaGetSymbolAddress((void**)&msgp,   g_msgp);
    cudaGetSymbolAddress((void**)&srcc,   g_srcc);
    cudaGetSymbolAddress((void**)&srcp,   g_srcp);
    cudaGetSymbolAddress((void**)&inv_mt, g_inv_mt);
    cudaGetSymbolAddress((void**)&inv_mc, g_inv_mc);
    cudaGetSymbolAddress((void**)&inv_it, g_inv_it);
    cudaGetSymbolAddress((void**)&inv_ip, g_inv_ip);
    cudaGetSymbolAddress((void**)&wt,     g_wt);

    cudaFuncSetAttribute(xform_gemm, cudaFuncAttributeMaxDynamicSharedMemorySize, SM1);
    cudaFuncSetAttribute(root_gemm,  cudaFuncAttributeMaxDynamicSharedMemorySize, SM1);

    // ---- weight prep ----
    prep_weights2<<<64, 256>>>(Wn, Wr, b_lin);
    prep_small<<<7, 128>>>(W_col, b_col, Wn, Wr, b_lin);

    // ---- degree inverses ----
    cudaMemsetAsync(inv_mt, 0, NT * sizeof(float));
    cudaMemsetAsync(inv_mc, 0, NC * sizeof(float));
    cudaMemsetAsync(inv_it, 0, NT * sizeof(float));
    cudaMemsetAsync(inv_ip, 0, NP * sizeof(float));
    count_edges<<<(EM + 255) / 256, 256>>>(em_dst, EM, inv_mt);
    count_edges<<<(EM + 255) / 256, 256>>>(em_src, EM, inv_mc);
    count_edges<<<(EI + 255) / 256, 256>>>(ei_dst, EI, inv_it);
    count_edges<<<(EI + 255) / 256, 256>>>(ei_src, EI, inv_ip);
    make_inv<<<(NT + 255) / 256, 256>>>(inv_mt, NT);
    make_inv<<<(NC + 255) / 256, 256>>>(inv_mc, NC);
    make_inv<<<(NT + 255) / 256, 256>>>(inv_it, NT);
    make_inv<<<(NP + 255) / 256, 256>>>(inv_ip, NP);

    // ---- layer 1 (all K=8, fused into scatter/combine) ----
    cudaMemsetAsync(msgm, 0, (size_t)NT * D * sizeof(float));
    cudaMemsetAsync(msgi, 0, (size_t)NT * D * sizeof(float));
    cudaMemsetAsync(msgc, 0, (size_t)NC * D * sizeof(float));
    cudaMemsetAsync(msgp, 0, (size_t)NP * D * sizeof(float));
    scatter8<<<(EM * 32 + 255) / 256, 256>>>(x_c, 0, em_src, em_dst, EM, msgm);
    scatter8<<<(EI * 32 + 255) / 256, 256>>>(x_p, 1, ei_src, ei_dst, EI, msgi);
    scatter8<<<(EM * 32 + 255) / 256, 256>>>(x_t, 3, em_dst, em_src, EM, msgc);
    scatter8<<<(EI * 32 + 255) / 256, 256>>>(x_t, 4, ei_dst, ei_src, EI, msgp);

    combine8<true ><<<((size_t)NT * 32 + 255) / 256, 256>>>(x_t, 2, msgm, inv_mt, msgi, inv_it, ht1, NT);
    combine8<false><<<((size_t)NC * 32 + 255) / 256, 256>>>(x_c, 5, msgc, inv_mc, nullptr, nullptr, hc1, NC);
    combine8<false><<<((size_t)NP * 32 + 255) / 256, 256>>>(x_p, 6, msgp, inv_ip, nullptr, nullptr, hp1, NP);

    // ---- layer 2 (K=128) ----
    xform_gemm<<<296, 256, SM1>>>(hc1, wt,         srcc, NC);
    xform_gemm<<<296, 256, SM1>>>(hp1, wt + 16384, srcp, NP);

    cudaMemsetAsync(msgm, 0, (size_t)NT * D * sizeof(float));
    cudaMemsetAsync(msgi, 0, (size_t)NT * D * sizeof(float));
    scatter_kernel<<<(EM * 32 + 255) / 256, 256>>>(srcc, em_src, em_dst, EM, msgm);
    scatter_kernel<<<(EI * 32 + 255) / 256, 256>>>(srcp, ei_src, ei_dst, EI, msgi);

    root_gemm<<<296, 256, SM1>>>(ht1, wt + 32768, wt + 49152,
                                 msgm, inv_mt, msgi, inv_it, ht2, NT);

    // ---- output head ----
    out_softmax<<<((size_t)NT * 32 + 255) / 256, 256>>>(ht2, W_out, b_out, out, NT);
}

// round 5
// speedup vs baseline: 10.7164x; 3.7050x over previous
#include <cuda_runtime.h>

// ---------------- problem sizes ----------------
#define NC 100000
#define NT 300000
#define NP 50000
#define EM 300000
#define EI 600000
#define NOUT 10

// ---------------- runtime aggregate scratch ----------------
__device__ float g_mc [(size_t)NC * 8];   // per-customer mean of x_t
__device__ float g_mp [(size_t)NP * 8];   // per-product mean of x_t
__device__ float g_mtc[(size_t)NT * 8];   // sum over t's customers of x_c
__device__ float g_mtp[(size_t)NT * 8];   // sum over t's products of x_p
__device__ float g_mmc[(size_t)NT * 8];   // sum over t's customers of m_c
__device__ float g_mmp[(size_t)NT * 8];   // sum over t's products of m_p
__device__ float g_fdc[NT];               // sum of delta_mc over t's customers
__device__ float g_fdp[NT];               // sum of delta_ip over t's products
__device__ float g_cnt_mt[NT];
__device__ float g_cnt_mc[NC];
__device__ float g_cnt_it[NT];
__device__ float g_cnt_ip[NP];

// ---------------- weight-prep scratch ----------------
__device__ float g_m1[7][1024];   // stage-1 [8,128] mats
__device__ float g_r1[7][128];    // stage-1 [128] rows
__device__ float g_m2[5][1024];   // stage-2 [8,128] mats
__device__ float g_r2[5][128];    // stage-2 [128] rows
__device__ float g_G[400];        // final [5][8][10]
__device__ float g_g[50];         // final [5][10]

// ---------------- weight prep ----------------
// Stage 1: fold embeds into layer-1 weights.
// mats: 0:T1x=0.5*Et(Wr0+Wr2) 1:T1c=0.5*Ec*Wn0 2:T1p=0.5*Ep*Wn2
//       3:C1x=Ec*Wr1 4:C1m=Et*Wn1 5:P1x=Ep*Wr3 6:P1m=Et*Wn3
// rows: 0:t1dm=0.5*ec*Wn0 1:t1di=0.5*ep*Wn2 2:t1const=0.5*(et(Wr0+Wr2)+b0+b2)
//       3:c1d=et*Wn1 4:c1const=ec*Wr1+b1 5:p1d=et*Wn3 6:p1const=ep*Wr3+b3
// (tables: 0=customer, 1=transaction, 2=product)
__global__ void prep1(const float* __restrict__ Wc, const float* __restrict__ bc,
                      const float* __restrict__ Wn, const float* __restrict__ Wr,
                      const float* __restrict__ bl) {
    int b = blockIdx.x, col = threadIdx.x;   // 128 threads
    if (b < 7) {
        int X = 0; const float* M1 = Wn; const float* M2 = nullptr; float s = 1.f;
        switch (b) {
            case 0: X = 1; M1 = Wr;             M2 = Wr + 2 * 16384; s = 0.5f; break;
            case 1: X = 0; M1 = Wn;             s = 0.5f; break;
            case 2: X = 2; M1 = Wn + 2 * 16384; s = 0.5f; break;
            case 3: X = 0; M1 = Wr + 1 * 16384; break;
            case 4: X = 1; M1 = Wn + 1 * 16384; break;
            case 5: X = 2; M1 = Wr + 3 * 16384; break;
            case 6: X = 1; M1 = Wn + 3 * 16384; break;
        }
        for (int f = 0; f < 8; f++) {
            float acc = 0.f;
            for (int d = 0; d < 16; d++) {
                int k = f * 16 + d;
                float m = M1[k * 128 + col];
                if (M2) m += M2[k * 128 + col];
                acc += Wc[X * 128 + k] * m;
            }
            g_m1[b][f * 128 + col] = s * acc;
        }
    } else {
        float t1dm = 0, t1di = 0, t1c = 0, c1d = 0, c1c = 0, p1d = 0, p1c = 0;
        for (int k = 0; k < 128; k++) {
            float bcu = bc[k], bt = bc[128 + k], bp = bc[256 + k];
            t1dm += bcu * Wn[k * 128 + col];
            t1di += bp  * Wn[2 * 16384 + k * 128 + col];
            t1c  += bt  * (Wr[k * 128 + col] + Wr[2 * 16384 + k * 128 + col]);
            c1d  += bt  * Wn[1 * 16384 + k * 128 + col];
            c1c  += bcu * Wr[1 * 16384 + k * 128 + col];
            p1d  += bt  * Wn[3 * 16384 + k * 128 + col];
            p1c  += bp  * Wr[3 * 16384 + k * 128 + col];
        }
        g_r1[0][col] = 0.5f * t1dm;
        g_r1[1][col] = 0.5f * t1di;
        g_r1[2][col] = 0.5f * (t1c + bl[0 * 128 + col] + bl[2 * 128 + col]);
        g_r1[3][col] = c1d;
        g_r1[4][col] = c1c + bl[1 * 128 + col];
        g_r1[5][col] = p1d;
        g_r1[6][col] = p1c + bl[3 * 128 + col];
    }
}

// Stage 2: chain through layer-2 (U=0.5*Wn[1,0], V=0.5*Wn[1,2], R=0.5*(Wr[1,0]+Wr[1,2]))
__global__ void prep2(const float* __restrict__ Wn, const float* __restrict__ Wr,
                      const float* __restrict__ bl) {
    int b = blockIdx.x, col = threadIdx.x;   // 128 threads
    const float* Un = Wn + 4 * 16384;
    const float* Vn = Wn + 6 * 16384;
    const float* R0 = Wr + 4 * 16384;
    const float* R2 = Wr + 6 * 16384;
    if (b < 5) {
        for (int f = 0; f < 8; f++) {
            float acc = 0.f;
            for (int k = 0; k < 128; k++) {
                float U = 0.5f * Un[k * 128 + col];
                float V = 0.5f * Vn[k * 128 + col];
                float R = 0.5f * (R0[k * 128 + col] + R2[k * 128 + col]);
                switch (b) {
                    case 0: acc += g_m1[0][f * 128 + k] * R; break;                                   // H_x
                    case 1: acc += g_m1[3][f * 128 + k] * U + g_m1[1][f * 128 + k] * R; break;        // H_mc
                    case 2: acc += g_m1[5][f * 128 + k] * V + g_m1[2][f * 128 + k] * R; break;        // H_mp
                    case 3: acc += g_m1[4][f * 128 + k] * U; break;                                   // H_mmc
                    case 4: acc += g_m1[6][f * 128 + k] * V; break;                                   // H_mmp
                }
            }
            g_m2[b][f * 128 + col] = acc;
        }
    } else {
        float fc = 0, fp = 0, dm = 0, di = 0, cc = 0;
        for (int k = 0; k < 128; k++) {
            float U = 0.5f * Un[k * 128 + col];
            float V = 0.5f * Vn[k * 128 + col];
            float R = 0.5f * (R0[k * 128 + col] + R2[k * 128 + col]);
            fc += g_r1[3][k] * U;
            fp += g_r1[5][k] * V;
            dm += g_r1[4][k] * U + g_r1[0][k] * R;
            di += g_r1[6][k] * V + g_r1[1][k] * R;
            cc += g_r1[2][k] * R;
        }
        g_r2[0][col] = fc;
        g_r2[1][col] = fp;
        g_r2[2][col] = dm;
        g_r2[3][col] = di;
        g_r2[4][col] = cc + 0.5f * (bl[4 * 128 + col] + bl[6 * 128 + col]);
    }
}

// Stage 3: project everything through W_out [128,10]
__global__ void prep3(const float* __restrict__ Wout, const float* __restrict__ bout) {
    int tid = threadIdx.x;   // 512
    if (tid < 400) {
        int m = tid / 80, f = (tid % 80) / 10, o = tid % 10;
        float acc = 0.f;
        for (int k = 0; k < 128; k++) acc += g_m2[m][f * 128 + k] * Wout[k * 10 + o];
        g_G[(m * 8 + f) * 10 + o] = acc;
    } else if (tid < 450) {
        int r = (tid - 400) / 10, o = (tid - 400) % 10;
        float acc = 0.f;
        for (int k = 0; k < 128; k++) acc += g_r2[r][k] * Wout[k * 10 + o];
        if (r == 4) acc += bout[o];
        g_g[r * 10 + o] = acc;
    }
}

// ---------------- runtime kernels ----------------
__global__ void count_edges(const int* __restrict__ dst, int E, float* __restrict__ cnt) {
    int e = blockIdx.x * blockDim.x + threadIdx.x;
    if (e < E) atomicAdd(cnt + dst[e], 1.0f);
}

__device__ __forceinline__ void red_add_v4(float* addr, float4 v) {
    asm volatile("red.global.add.v4.f32 [%0], {%1,%2,%3,%4};"
                 :: "l"(addr), "f"(v.x), "f"(v.y), "f"(v.z), "f"(v.w)
                 : "memory");
}

// 2 threads per edge: scatter-add an 8-float feature row
__global__ void scat8(const float* __restrict__ feat,
                      const int* __restrict__ fidx, const int* __restrict__ didx,
                      int E, float* __restrict__ out) {
    int g = blockIdx.x * blockDim.x + threadIdx.x;
    int e = g >> 1, h = g & 1;
    if (e >= E) return;
    float4 v = ((const float4*)(feat + (size_t)fidx[e] * 8))[h];
    red_add_v4(out + (size_t)didx[e] * 8 + h * 4, v);
}

// scalar scatter of delta flags (src has >=1 neighbor)
__global__ void scat_delta(const float* __restrict__ cnt,
                           const int* __restrict__ fidx, const int* __restrict__ didx,
                           int E, float* __restrict__ out) {
    int e = blockIdx.x * blockDim.x + threadIdx.x;
    if (e >= E) return;
    atomicAdd(out + didx[e], cnt[fidx[e]] > 0.f ? 1.f : 0.f);
}

// scale 8-float sums to means
__global__ void make_mean8(float* __restrict__ m, const float* __restrict__ cnt, int n) {
    int g = blockIdx.x * blockDim.x + threadIdx.x;
    int i = g >> 1, h = g & 1;
    if (i >= n) return;
    float iv = 1.f / fmaxf(cnt[i], 1.f);
    float4* p = (float4*)(m + (size_t)i * 8) + h;
    float4 v = *p;
    v.x *= iv; v.y *= iv; v.z *= iv; v.w *= iv;
    *p = v;
}

// ---------------- final: 44-feature linear model + softmax ----------------
__global__ __launch_bounds__(256)
void final_kernel(const float* __restrict__ xt, float* __restrict__ out) {
    __shared__ float sG[400];
    __shared__ float sg[50];
    int tid = threadIdx.x;
    for (int i = tid; i < 400; i += 256) sG[i] = g_G[i];
    if (tid < 50) sg[tid] = g_g[tid];
    __syncthreads();

    int t = blockIdx.x * 256 + tid;
    if (t >= NT) return;

    float cm = g_cnt_mt[t], ci = g_cnt_it[t];
    float im = 1.f / fmaxf(cm, 1.f);
    float ii = 1.f / fmaxf(ci, 1.f);
    float dm = cm > 0.f ? 1.f : 0.f;
    float di = ci > 0.f ? 1.f : 0.f;

    float feat[40];
    {
        const float4* p;
        p = (const float4*)(xt + (size_t)t * 8);
        float4 a = p[0], b = p[1];
        feat[0]=a.x; feat[1]=a.y; feat[2]=a.z; feat[3]=a.w;
        feat[4]=b.x; feat[5]=b.y; feat[6]=b.z; feat[7]=b.w;
        p = (const float4*)(g_mtc + (size_t)t * 8); a = p[0]; b = p[1];
        feat[8]=a.x*im; feat[9]=a.y*im; feat[10]=a.z*im; feat[11]=a.w*im;
        feat[12]=b.x*im; feat[13]=b.y*im; feat[14]=b.z*im; feat[15]=b.w*im;
        p = (const float4*)(g_mtp + (size_t)t * 8); a = p[0]; b = p[1];
        feat[16]=a.x*ii; feat[17]=a.y*ii; feat[18]=a.z*ii; feat[19]=a.w*ii;
        feat[20]=b.x*ii; feat[21]=b.y*ii; feat[22]=b.z*ii; feat[23]=b.w*ii;
        p = (const float4*)(g_mmc + (size_t)t * 8); a = p[0]; b = p[1];
        feat[24]=a.x*im; feat[25]=a.y*im; feat[26]=a.z*im; feat[27]=a.w*im;
        feat[28]=b.x*im; feat[29]=b.y*im; feat[30]=b.z*im; feat[31]=b.w*im;
        p = (const float4*)(g_mmp + (size_t)t * 8); a = p[0]; b = p[1];
        feat[32]=a.x*ii; feat[33]=a.y*ii; feat[34]=a.z*ii; feat[35]=a.w*ii;
        feat[36]=b.x*ii; feat[37]=b.y*ii; feat[38]=b.z*ii; feat[39]=b.w*ii;
    }
    float fdc = g_fdc[t] * im;
    float fdp = g_fdp[t] * ii;

    float p[NOUT];
    #pragma unroll
    for (int o = 0; o < NOUT; o++) {
        float s = sg[40 + o];
        s = fmaf(fdc, sg[o],      s);
        s = fmaf(fdp, sg[10 + o], s);
        s = fmaf(dm,  sg[20 + o], s);
        s = fmaf(di,  sg[30 + o], s);
        p[o] = s;
    }
    #pragma unroll
    for (int f = 0; f < 40; f++) {
        float xv = feat[f];
        #pragma unroll
        for (int o = 0; o < NOUT; o++) p[o] = fmaf(xv, sG[f * 10 + o], p[o]);
    }

    float m = p[0];
    #pragma unroll
    for (int o = 1; o < NOUT; o++) m = fmaxf(m, p[o]);
    float sum = 0.f;
    #pragma unroll
    for (int o = 0; o < NOUT; o++) { p[o] = expf(p[o] - m); sum += p[o]; }
    float isum = 1.0f / sum;
    #pragma unroll
    for (int o = 0; o < NOUT; o++) out[(size_t)t * NOUT + o] = p[o] * isum;
}

// ---------------- host orchestration ----------------
extern "C" void kernel_launch(void* const* d_in, const int* in_sizes, int n_in,
                              void* d_out, int out_size) {
    const float* x_c   = (const float*)d_in[0];
    const float* x_t   = (const float*)d_in[1];
    const float* x_p   = (const float*)d_in[2];
    const float* W_col = (const float*)d_in[3];
    const float* b_col = (const float*)d_in[4];
    const float* Wn    = (const float*)d_in[5];
    const float* Wr    = (const float*)d_in[6];
    const float* b_lin = (const float*)d_in[7];
    const float* W_out = (const float*)d_in[8];
    const float* b_out = (const float*)d_in[9];
    const int* em_src  = (const int*)d_in[10];
    const int* em_dst  = (const int*)d_in[11];
    const int* ei_src  = (const int*)d_in[12];
    const int* ei_dst  = (const int*)d_in[13];
    float* out = (float*)d_out;

    float *mc, *mp, *mtc, *mtp, *mmc, *mmp, *fdc, *fdp;
    float *cnt_mt, *cnt_mc, *cnt_it, *cnt_ip;
    cudaGetSymbolAddress((void**)&mc,  g_mc);
    cudaGetSymbolAddress((void**)&mp,  g_mp);
    cudaGetSymbolAddress((void**)&mtc, g_mtc);
    cudaGetSymbolAddress((void**)&mtp, g_mtp);
    cudaGetSymbolAddress((void**)&mmc, g_mmc);
    cudaGetSymbolAddress((void**)&mmp, g_mmp);
    cudaGetSymbolAddress((void**)&fdc, g_fdc);
    cudaGetSymbolAddress((void**)&fdp, g_fdp);
    cudaGetSymbolAddress((void**)&cnt_mt, g_cnt_mt);
    cudaGetSymbolAddress((void**)&cnt_mc, g_cnt_mc);
    cudaGetSymbolAddress((void**)&cnt_it, g_cnt_it);
    cudaGetSymbolAddress((void**)&cnt_ip, g_cnt_ip);

    // ---- weight prep (independent of graph data) ----
    prep1<<<8, 128>>>(W_col, b_col, Wn, Wr, b_lin);
    prep2<<<6, 128>>>(Wn, Wr, b_lin);
    prep3<<<1, 512>>>(W_out, b_out);

    // ---- zero accumulators ----
    cudaMemsetAsync(cnt_mt, 0, NT * sizeof(float));
    cudaMemsetAsync(cnt_mc, 0, NC * sizeof(float));
    cudaMemsetAsync(cnt_it, 0, NT * sizeof(float));
    cudaMemsetAsync(cnt_ip, 0, NP * sizeof(float));
    cudaMemsetAsync(mc,  0, (size_t)NC * 8 * sizeof(float));
    cudaMemsetAsync(mp,  0, (size_t)NP * 8 * sizeof(float));
    cudaMemsetAsync(mtc, 0, (size_t)NT * 8 * sizeof(float));
    cudaMemsetAsync(mtp, 0, (size_t)NT * 8 * sizeof(float));
    cudaMemsetAsync(mmc, 0, (size_t)NT * 8 * sizeof(float));
    cudaMemsetAsync(mmp, 0, (size_t)NT * 8 * sizeof(float));
    cudaMemsetAsync(fdc, 0, NT * sizeof(float));
    cudaMemsetAsync(fdp, 0, NP > NT ? NP * sizeof(float) : NT * sizeof(float));

    // ---- degrees ----
    count_edges<<<(EM + 255) / 256, 256>>>(em_dst, EM, cnt_mt);
    count_edges<<<(EM + 255) / 256, 256>>>(em_src, EM, cnt_mc);
    count_edges<<<(EI + 255) / 256, 256>>>(ei_dst, EI, cnt_it);
    count_edges<<<(EI + 255) / 256, 256>>>(ei_src, EI, cnt_ip);

    // ---- 1-hop 8-dim aggregates ----
    scat8<<<(2 * EM + 255) / 256, 256>>>(x_c, em_src, em_dst, EM, mtc);  // x_c -> t
    scat8<<<(2 * EM + 255) / 256, 256>>>(x_t, em_dst, em_src, EM, mc);   // x_t -> c
    scat8<<<(2 * EI + 255) / 256, 256>>>(x_p, ei_src, ei_dst, EI, mtp);  // x_p -> t
    scat8<<<(2 * EI + 255) / 256, 256>>>(x_t, ei_dst, ei_src, EI, mp);   // x_t -> p

    // scale m_c / m_p to means (needed before 2-hop)
    make_mean8<<<(2 * NC + 255) / 256, 256>>>(mc, cnt_mc, NC);
    make_mean8<<<(2 * NP + 255) / 256, 256>>>(mp, cnt_ip, NP);

    // ---- 2-hop aggregates + delta fractions ----
    scat8<<<(2 * EM + 255) / 256, 256>>>(mc, em_src, em_dst, EM, mmc);   // m_c -> t
    scat8<<<(2 * EI + 255) / 256, 256>>>(mp, ei_src, ei_dst, EI, mmp);   // m_p -> t
    scat_delta<<<(EM + 255) / 256, 256>>>(cnt_mc, em_src, em_dst, EM, fdc);
    scat_delta<<<(EI + 255) / 256, 256>>>(cnt_ip, ei_src, ei_dst, EI, fdp);

    // ---- final linear model + softmax ----
    final_kernel<<<(NT + 255) / 256, 256>>>(x_t, out);
}

// round 6
// speedup vs baseline: 11.0118x; 1.0276x over previous
#include <cuda_runtime.h>

// ---------------- problem sizes ----------------
#define NC 100000
#define NT 300000
#define NP 50000
#define EM 300000
#define EI 600000
#define NOUT 10

// ---------------- one contiguous zeroed scratch block ----------------
// layout (floats):
#define OFF_MTC   0                               // [NT*8] sum x_c over t's customers
#define OFF_MTP   (OFF_MTC + (size_t)NT * 8)      // [NT*8] sum x_p over t's products
#define OFF_MMC   (OFF_MTP + (size_t)NT * 8)      // [NT*8] sum m_c over t's customers
#define OFF_MMP   (OFF_MMC + (size_t)NT * 8)      // [NT*8] sum m_p over t's products
#define OFF_MCS   (OFF_MMP + (size_t)NT * 8)      // [NC*8] sum x_t over c's transactions
#define OFF_MPS   (OFF_MCS + (size_t)NC * 8)      // [NP*8] sum x_t over p's transactions
#define OFF_CMT   (OFF_MPS + (size_t)NP * 8)      // [NT] deg(t, makes)
#define OFF_CIT   (OFF_CMT + NT)                  // [NT] deg(t, in)
#define OFF_CMC   (OFF_CIT + NT)                  // [NC] deg(c)
#define OFF_CIP   (OFF_CMC + NC)                  // [NP] deg(p)
#define OFF_FDC   (OFF_CIP + NP)                  // [NT] sum delta_c
#define OFF_FDP   (OFF_FDC + NT)                  // [NT] sum delta_p
#define SCR_TOTAL (OFF_FDP + NT)

__device__ float g_scr[SCR_TOTAL];

// ---------------- weight-prep scratch ----------------
__device__ float g_m1[7][1024];   // stage-1 [8,128] mats
__device__ float g_r1[7][128];    // stage-1 [128] rows
__device__ float g_m2[5][1024];   // stage-2 [8,128] mats
__device__ float g_r2[5][128];    // stage-2 [128] rows
__device__ float g_G[400];        // final [5][8][10]
__device__ float g_g[50];         // final [5][10]

// ---------------- weight prep (unchanged closed-form chain) ----------------
__global__ void prep1(const float* __restrict__ Wc, const float* __restrict__ bc,
                      const float* __restrict__ Wn, const float* __restrict__ Wr,
                      const float* __restrict__ bl) {
    int b = blockIdx.x, col = threadIdx.x;   // 128 threads
    if (b < 7) {
        int X = 0; const float* M1 = Wn; const float* M2 = nullptr; float s = 1.f;
        switch (b) {
            case 0: X = 1; M1 = Wr;             M2 = Wr + 2 * 16384; s = 0.5f; break;
            case 1: X = 0; M1 = Wn;             s = 0.5f; break;
            case 2: X = 2; M1 = Wn + 2 * 16384; s = 0.5f; break;
            case 3: X = 0; M1 = Wr + 1 * 16384; break;
            case 4: X = 1; M1 = Wn + 1 * 16384; break;
            case 5: X = 2; M1 = Wr + 3 * 16384; break;
            case 6: X = 1; M1 = Wn + 3 * 16384; break;
        }
        for (int f = 0; f < 8; f++) {
            float acc = 0.f;
            for (int d = 0; d < 16; d++) {
                int k = f * 16 + d;
                float m = M1[k * 128 + col];
                if (M2) m += M2[k * 128 + col];
                acc += Wc[X * 128 + k] * m;
            }
            g_m1[b][f * 128 + col] = s * acc;
        }
    } else {
        float t1dm = 0, t1di = 0, t1c = 0, c1d = 0, c1c = 0, p1d = 0, p1c = 0;
        for (int k = 0; k < 128; k++) {
            float bcu = bc[k], bt = bc[128 + k], bp = bc[256 + k];
            t1dm += bcu * Wn[k * 128 + col];
            t1di += bp  * Wn[2 * 16384 + k * 128 + col];
            t1c  += bt  * (Wr[k * 128 + col] + Wr[2 * 16384 + k * 128 + col]);
            c1d  += bt  * Wn[1 * 16384 + k * 128 + col];
            c1c  += bcu * Wr[1 * 16384 + k * 128 + col];
            p1d  += bt  * Wn[3 * 16384 + k * 128 + col];
            p1c  += bp  * Wr[3 * 16384 + k * 128 + col];
        }
        g_r1[0][col] = 0.5f * t1dm;
        g_r1[1][col] = 0.5f * t1di;
        g_r1[2][col] = 0.5f * (t1c + bl[0 * 128 + col] + bl[2 * 128 + col]);
        g_r1[3][col] = c1d;
        g_r1[4][col] = c1c + bl[1 * 128 + col];
        g_r1[5][col] = p1d;
        g_r1[6][col] = p1c + bl[3 * 128 + col];
    }
}

__global__ void prep2(const float* __restrict__ Wn, const float* __restrict__ Wr,
                      const float* __restrict__ bl) {
    int b = blockIdx.x, col = threadIdx.x;   // 128 threads
    const float* Un = Wn + 4 * 16384;
    const float* Vn = Wn + 6 * 16384;
    const float* R0 = Wr + 4 * 16384;
    const float* R2 = Wr + 6 * 16384;
    if (b < 5) {
        for (int f = 0; f < 8; f++) {
            float acc = 0.f;
            for (int k = 0; k < 128; k++) {
                float U = 0.5f * Un[k * 128 + col];
                float V = 0.5f * Vn[k * 128 + col];
                float R = 0.5f * (R0[k * 128 + col] + R2[k * 128 + col]);
                switch (b) {
                    case 0: acc += g_m1[0][f * 128 + k] * R; break;
                    case 1: acc += g_m1[3][f * 128 + k] * U + g_m1[1][f * 128 + k] * R; break;
                    case 2: acc += g_m1[5][f * 128 + k] * V + g_m1[2][f * 128 + k] * R; break;
                    case 3: acc += g_m1[4][f * 128 + k] * U; break;
                    case 4: acc += g_m1[6][f * 128 + k] * V; break;
                }
            }
            g_m2[b][f * 128 + col] = acc;
        }
    } else {
        float fc = 0, fp = 0, dm = 0, di = 0, cc = 0;
        for (int k = 0; k < 128; k++) {
            float U = 0.5f * Un[k * 128 + col];
            float V = 0.5f * Vn[k * 128 + col];
            float R = 0.5f * (R0[k * 128 + col] + R2[k * 128 + col]);
            fc += g_r1[3][k] * U;
            fp += g_r1[5][k] * V;
            dm += g_r1[4][k] * U + g_r1[0][k] * R;
            di += g_r1[6][k] * V + g_r1[1][k] * R;
            cc += g_r1[2][k] * R;
        }
        g_r2[0][col] = fc;
        g_r2[1][col] = fp;
        g_r2[2][col] = dm;
        g_r2[3][col] = di;
        g_r2[4][col] = cc + 0.5f * (bl[4 * 128 + col] + bl[6 * 128 + col]);
    }
}

__global__ void prep3(const float* __restrict__ Wout, const float* __restrict__ bout) {
    int tid = threadIdx.x;   // 512
    if (tid < 400) {
        int m = tid / 80, f = (tid % 80) / 10, o = tid % 10;
        float acc = 0.f;
        for (int k = 0; k < 128; k++) acc += g_m2[m][f * 128 + k] * Wout[k * 10 + o];
        g_G[(m * 8 + f) * 10 + o] = acc;
    } else if (tid < 450) {
        int r = (tid - 400) / 10, o = (tid - 400) % 10;
        float acc = 0.f;
        for (int k = 0; k < 128; k++) acc += g_r2[r][k] * Wout[k * 10 + o];
        if (r == 4) acc += bout[o];
        g_g[r * 10 + o] = acc;
    }
}

// ---------------- atomics ----------------
__device__ __forceinline__ void red_add_v4(float* addr, float4 v) {
    asm volatile("red.global.add.v4.f32 [%0], {%1,%2,%3,%4};"
                 :: "l"(addr), "f"(v.x), "f"(v.y), "f"(v.z), "f"(v.w)
                 : "memory");
}
__device__ __forceinline__ void red_add_f(float* addr, float v) {
    asm volatile("red.global.add.f32 [%0], %1;" :: "l"(addr), "f"(v) : "memory");
}

// ---------------- phase 1: bidirectional feature scatter + degree counts ----------------
// 2 threads per edge. h=lane parity selects the float4 half.
//   aggd[dst] += xs[src];  aggs[src] += xd[dst];  cntd[dst]++;  cnts[src]++.
__global__ __launch_bounds__(256)
void phase1(const float* __restrict__ xs, const float* __restrict__ xd,
            const int* __restrict__ src, const int* __restrict__ dst, int E,
            float* __restrict__ aggd, float* __restrict__ aggs,
            float* __restrict__ cntd, float* __restrict__ cnts) {
    int g = blockIdx.x * blockDim.x + threadIdx.x;
    int e = g >> 1, h = g & 1;
    if (e >= E) return;
    int s = __ldg(src + e);
    int d = __ldg(dst + e);
    float4 vs = ((const float4*)(xs + (size_t)s * 8))[h];
    float4 vd = ((const float4*)(xd + (size_t)d * 8))[h];
    red_add_v4(aggd + (size_t)d * 8 + h * 4, vs);
    red_add_v4(aggs + (size_t)s * 8 + h * 4, vd);
    if (h == 0) {
        red_add_f(cntd + d, 1.0f);
        red_add_f(cnts + s, 1.0f);
    }
}

// ---------------- phase 2: 2-hop mean scatter + delta flags ----------------
// mm[dst] += msum[src]/max(cnt[src],1);  fd[dst] += (cnt[src]>0).
__global__ __launch_bounds__(256)
void phase2(const float* __restrict__ msum, const float* __restrict__ cnt,
            const int* __restrict__ src, const int* __restrict__ dst, int E,
            float* __restrict__ mm, float* __restrict__ fd) {
    int g = blockIdx.x * blockDim.x + threadIdx.x;
    int e = g >> 1, h = g & 1;
    if (e >= E) return;
    int s = __ldg(src + e);
    int d = __ldg(dst + e);
    float c  = __ldg(cnt + s);
    float iv = 1.0f / fmaxf(c, 1.0f);
    float4 v = ((const float4*)(msum + (size_t)s * 8))[h];
    v.x *= iv; v.y *= iv; v.z *= iv; v.w *= iv;
    red_add_v4(mm + (size_t)d * 8 + h * 4, v);
    if (h == 0) red_add_f(fd + d, c > 0.f ? 1.0f : 0.0f);
}

// ---------------- final: 44-feature linear model + softmax ----------------
__global__ __launch_bounds__(256)
void final_kernel(const float* __restrict__ xt, float* __restrict__ out) {
    __shared__ float sG[400];
    __shared__ float sg[50];
    int tid = threadIdx.x;
    for (int i = tid; i < 400; i += 256) sG[i] = g_G[i];
    if (tid < 50) sg[tid] = g_g[tid];
    __syncthreads();

    int t = blockIdx.x * 256 + tid;
    if (t >= NT) return;

    float cm = g_scr[OFF_CMT + t], ci = g_scr[OFF_CIT + t];
    float im = 1.f / fmaxf(cm, 1.f);
    float ii = 1.f / fmaxf(ci, 1.f);
    float dm = cm > 0.f ? 1.f : 0.f;
    float di = ci > 0.f ? 1.f : 0.f;

    float feat[40];
    {
        const float4* p;
        float4 a, b;
        p = (const float4*)(xt + (size_t)t * 8); a = p[0]; b = p[1];
        feat[0]=a.x; feat[1]=a.y; feat[2]=a.z; feat[3]=a.w;
        feat[4]=b.x; feat[5]=b.y; feat[6]=b.z; feat[7]=b.w;
        p = (const float4*)(g_scr + OFF_MTC + (size_t)t * 8); a = p[0]; b = p[1];
        feat[8]=a.x*im; feat[9]=a.y*im; feat[10]=a.z*im; feat[11]=a.w*im;
        feat[12]=b.x*im; feat[13]=b.y*im; feat[14]=b.z*im; feat[15]=b.w*im;
        p = (const float4*)(g_scr + OFF_MTP + (size_t)t * 8); a = p[0]; b = p[1];
        feat[16]=a.x*ii; feat[17]=a.y*ii; feat[18]=a.z*ii; feat[19]=a.w*ii;
        feat[20]=b.x*ii; feat[21]=b.y*ii; feat[22]=b.z*ii; feat[23]=b.w*ii;
        p = (const float4*)(g_scr + OFF_MMC + (size_t)t * 8); a = p[0]; b = p[1];
        feat[24]=a.x*im; feat[25]=a.y*im; feat[26]=a.z*im; feat[27]=a.w*im;
        feat[28]=b.x*im; feat[29]=b.y*im; feat[30]=b.z*im; feat[31]=b.w*im;
        p = (const float4*)(g_scr + OFF_MMP + (size_t)t * 8); a = p[0]; b = p[1];
        feat[32]=a.x*ii; feat[33]=a.y*ii; feat[34]=a.z*ii; feat[35]=a.w*ii;
        feat[36]=b.x*ii; feat[37]=b.y*ii; feat[38]=b.z*ii; feat[39]=b.w*ii;
    }
    float fdc = g_scr[OFF_FDC + t] * im;
    float fdp = g_scr[OFF_FDP + t] * ii;

    float p[NOUT];
    #pragma unroll
    for (int o = 0; o < NOUT; o++) {
        float s = sg[40 + o];
        s = fmaf(fdc, sg[o],      s);
        s = fmaf(fdp, sg[10 + o], s);
        s = fmaf(dm,  sg[20 + o], s);
        s = fmaf(di,  sg[30 + o], s);
        p[o] = s;
    }
    #pragma unroll
    for (int f = 0; f < 40; f++) {
        float xv = feat[f];
        #pragma unroll
        for (int o = 0; o < NOUT; o++) p[o] = fmaf(xv, sG[f * 10 + o], p[o]);
    }

    float m = p[0];
    #pragma unroll
    for (int o = 1; o < NOUT; o++) m = fmaxf(m, p[o]);
    float sum = 0.f;
    #pragma unroll
    for (int o = 0; o < NOUT; o++) { p[o] = expf(p[o] - m); sum += p[o]; }
    float isum = 1.0f / sum;
    #pragma unroll
    for (int o = 0; o < NOUT; o++) out[(size_t)t * NOUT + o] = p[o] * isum;
}

// ---------------- host orchestration ----------------
extern "C" void kernel_launch(void* const* d_in, const int* in_sizes, int n_in,
                              void* d_out, int out_size) {
    const float* x_c   = (const float*)d_in[0];
    const float* x_t   = (const float*)d_in[1];
    const float* x_p   = (const float*)d_in[2];
    const float* W_col = (const float*)d_in[3];
    const float* b_col = (const float*)d_in[4];
    const float* Wn    = (const float*)d_in[5];
    const float* Wr    = (const float*)d_in[6];
    const float* b_lin = (const float*)d_in[7];
    const float* W_out = (const float*)d_in[8];
    const float* b_out = (const float*)d_in[9];
    const int* em_src  = (const int*)d_in[10];
    const int* em_dst  = (const int*)d_in[11];
    const int* ei_src  = (const int*)d_in[12];
    const int* ei_dst  = (const int*)d_in[13];
    float* out = (float*)d_out;

    float* scr;
    cudaGetSymbolAddress((void**)&scr, g_scr);

    // 1) zero all accumulators in one node
    cudaMemsetAsync(scr, 0, SCR_TOTAL * sizeof(float));

    // 2) closed-form weight chain (independent of graph)
    prep1<<<8, 128>>>(W_col, b_col, Wn, Wr, b_lin);
    prep2<<<6, 128>>>(Wn, Wr, b_lin);
    prep3<<<1, 512>>>(W_out, b_out);

    // 3) phase-1: bidirectional 1-hop sums + degrees (one kernel per edge list)
    phase1<<<(2 * EM + 255) / 256, 256>>>(x_c, x_t, em_src, em_dst, EM,
                                          scr + OFF_MTC, scr + OFF_MCS,
                                          scr + OFF_CMT, scr + OFF_CMC);
    phase1<<<(2 * EI + 255) / 256, 256>>>(x_p, x_t, ei_src, ei_dst, EI,
                                          scr + OFF_MTP, scr + OFF_MPS,
                                          scr + OFF_CIT, scr + OFF_CIP);

    // 4) phase-2: 2-hop mean scatter + delta fractions
    phase2<<<(2 * EM + 255) / 256, 256>>>(scr + OFF_MCS, scr + OFF_CMC,
                                          em_src, em_dst, EM,
                                          scr + OFF_MMC, scr + OFF_FDC);
    phase2<<<(2 * EI + 255) / 256, 256>>>(scr + OFF_MPS, scr + OFF_CIP,
                                          ei_src, ei_dst, EI,
                                          scr + OFF_MMP, scr + OFF_FDP);

    // 5) final linear model + softmax
    final_kernel<<<(NT + 255) / 256, 256>>>(x_t, out);
}

// round 7
// speedup vs baseline: 25.4340x; 2.3097x over previous
#include <cuda_runtime.h>

// ---------------- problem sizes ----------------
#define NC 100000
#define NT 300000
#define NP 50000
#define EM 300000
#define EI 600000
#define NOUT 10

// ---------------- one contiguous zeroed scratch block ----------------
#define OFF_MTC   0                               // [NT*8] sum x_c over t's customers
#define OFF_MTP   (OFF_MTC + (size_t)NT * 8)      // [NT*8] sum x_p over t's products
#define OFF_MMC   (OFF_MTP + (size_t)NT * 8)      // [NT*8] sum m_c over t's customers
#define OFF_MMP   (OFF_MMC + (size_t)NT * 8)      // [NT*8] sum m_p over t's products
#define OFF_MCS   (OFF_MMP + (size_t)NT * 8)      // [NC*8] sum x_t over c's transactions
#define OFF_MPS   (OFF_MCS + (size_t)NC * 8)      // [NP*8] sum x_t over p's transactions
#define OFF_CMT   (OFF_MPS + (size_t)NP * 8)      // [NT] deg(t, makes)
#define OFF_CIT   (OFF_CMT + NT)                  // [NT] deg(t, in)
#define OFF_CMC   (OFF_CIT + NT)                  // [NC] deg(c)
#define OFF_CIP   (OFF_CMC + NC)                  // [NP] deg(p)
#define OFF_FDC   (OFF_CIP + NP)                  // [NT] sum delta_c
#define OFF_FDP   (OFF_FDC + NT)                  // [NT] sum delta_p
#define SCR_TOTAL (OFF_FDP + NT)

__device__ float g_scr[SCR_TOTAL];

// ---------------- weight-prep scratch ----------------
__device__ float g_m1[7][1024];
__device__ float g_r1[7][128];
__device__ float g_m2[5][1024];
__device__ float g_r2[5][128];
__device__ float g_G[400];
__device__ float g_g[50];

// ---------------- weight prep (parallelized closed-form chain) ----------------
// prep1: blocks 0-6 = mats, blocks 7-13 = bias rows (one row per block)
__global__ void prep1(const float* __restrict__ Wc, const float* __restrict__ bc,
                      const float* __restrict__ Wn, const float* __restrict__ Wr,
                      const float* __restrict__ bl) {
    int b = blockIdx.x, col = threadIdx.x;   // 128 threads
    if (b < 7) {
        int X = 0; const float* M1 = Wn; const float* M2 = nullptr; float s = 1.f;
        switch (b) {
            case 0: X = 1; M1 = Wr;             M2 = Wr + 2 * 16384; s = 0.5f; break;
            case 1: X = 0; M1 = Wn;             s = 0.5f; break;
            case 2: X = 2; M1 = Wn + 2 * 16384; s = 0.5f; break;
            case 3: X = 0; M1 = Wr + 1 * 16384; break;
            case 4: X = 1; M1 = Wn + 1 * 16384; break;
            case 5: X = 2; M1 = Wr + 3 * 16384; break;
            case 6: X = 1; M1 = Wn + 3 * 16384; break;
        }
        #pragma unroll 2
        for (int f = 0; f < 8; f++) {
            float acc = 0.f;
            #pragma unroll 4
            for (int d = 0; d < 16; d++) {
                int k = f * 16 + d;
                float m = M1[k * 128 + col];
                if (M2) m += M2[k * 128 + col];
                acc += Wc[X * 128 + k] * m;
            }
            g_m1[b][f * 128 + col] = s * acc;
        }
    } else {
        int r = b - 7;
        float acc = 0.f;
        switch (r) {
            case 0:
                #pragma unroll 8
                for (int k = 0; k < 128; k++) acc += bc[k] * Wn[k * 128 + col];
                g_r1[0][col] = 0.5f * acc; break;
            case 1:
                #pragma unroll 8
                for (int k = 0; k < 128; k++) acc += bc[256 + k] * Wn[2 * 16384 + k * 128 + col];
                g_r1[1][col] = 0.5f * acc; break;
            case 2:
                #pragma unroll 8
                for (int k = 0; k < 128; k++)
                    acc += bc[128 + k] * (Wr[k * 128 + col] + Wr[2 * 16384 + k * 128 + col]);
                g_r1[2][col] = 0.5f * (acc + bl[0 * 128 + col] + bl[2 * 128 + col]); break;
            case 3:
                #pragma unroll 8
                for (int k = 0; k < 128; k++) acc += bc[128 + k] * Wn[1 * 16384 + k * 128 + col];
                g_r1[3][col] = acc; break;
            case 4:
                #pragma unroll 8
                for (int k = 0; k < 128; k++) acc += bc[k] * Wr[1 * 16384 + k * 128 + col];
                g_r1[4][col] = acc + bl[1 * 128 + col]; break;
            case 5:
                #pragma unroll 8
                for (int k = 0; k < 128; k++) acc += bc[128 + k] * Wn[3 * 16384 + k * 128 + col];
                g_r1[5][col] = acc; break;
            case 6:
                #pragma unroll 8
                for (int k = 0; k < 128; k++) acc += bc[256 + k] * Wr[3 * 16384 + k * 128 + col];
                g_r1[6][col] = acc + bl[3 * 128 + col]; break;
        }
    }
}

// prep2: blocks 0-39 = (mat m = b/8, f = b%8); blocks 40-44 = rows
__global__ void prep2(const float* __restrict__ Wn, const float* __restrict__ Wr,
                      const float* __restrict__ bl) {
    int b = blockIdx.x, col = threadIdx.x;   // 128 threads
    const float* Un = Wn + 4 * 16384;
    const float* Vn = Wn + 6 * 16384;
    const float* R0 = Wr + 4 * 16384;
    const float* R2 = Wr + 6 * 16384;
    if (b < 40) {
        int m = b >> 3, f = b & 7;
        float acc = 0.f;
        #pragma unroll 4
        for (int k = 0; k < 128; k++) {
            float w = 0.f;
            switch (m) {
                case 0: w = g_m1[0][f * 128 + k] * 0.5f * (R0[k * 128 + col] + R2[k * 128 + col]); break;
                case 1: w = g_m1[3][f * 128 + k] * 0.5f * Un[k * 128 + col]
                          + g_m1[1][f * 128 + k] * 0.5f * (R0[k * 128 + col] + R2[k * 128 + col]); break;
                case 2: w = g_m1[5][f * 128 + k] * 0.5f * Vn[k * 128 + col]
                          + g_m1[2][f * 128 + k] * 0.5f * (R0[k * 128 + col] + R2[k * 128 + col]); break;
                case 3: w = g_m1[4][f * 128 + k] * 0.5f * Un[k * 128 + col]; break;
                case 4: w = g_m1[6][f * 128 + k] * 0.5f * Vn[k * 128 + col]; break;
            }
            acc += w;
        }
        g_m2[m][f * 128 + col] = acc;
    } else {
        int r = b - 40;
        float acc = 0.f;
        #pragma unroll 4
        for (int k = 0; k < 128; k++) {
            float U = 0.5f * Un[k * 128 + col];
            float V = 0.5f * Vn[k * 128 + col];
            float R = 0.5f * (R0[k * 128 + col] + R2[k * 128 + col]);
            switch (r) {
                case 0: acc += g_r1[3][k] * U; break;
                case 1: acc += g_r1[5][k] * V; break;
                case 2: acc += g_r1[4][k] * U + g_r1[0][k] * R; break;
                case 3: acc += g_r1[6][k] * V + g_r1[1][k] * R; break;
                case 4: acc += g_r1[2][k] * R; break;
            }
        }
        if (r == 4) acc += 0.5f * (bl[4 * 128 + col] + bl[6 * 128 + col]);
        g_r2[r][col] = acc;
    }
}

__global__ void prep3(const float* __restrict__ Wout, const float* __restrict__ bout) {
    int tid = threadIdx.x;   // 512
    if (tid < 400) {
        int m = tid / 80, f = (tid % 80) / 10, o = tid % 10;
        float acc = 0.f;
        #pragma unroll 8
        for (int k = 0; k < 128; k++) acc += g_m2[m][f * 128 + k] * Wout[k * 10 + o];
        g_G[(m * 8 + f) * 10 + o] = acc;
    } else if (tid < 450) {
        int r = (tid - 400) / 10, o = (tid - 400) % 10;
        float acc = 0.f;
        #pragma unroll 8
        for (int k = 0; k < 128; k++) acc += g_r2[r][k] * Wout[k * 10 + o];
        if (r == 4) acc += bout[o];
        g_g[r * 10 + o] = acc;
    }
}

// ---------------- atomics ----------------
__device__ __forceinline__ void red_add_v4(float* addr, float4 v) {
    asm volatile("red.global.add.v4.f32 [%0], {%1,%2,%3,%4};"
                 :: "l"(addr), "f"(v.x), "f"(v.y), "f"(v.z), "f"(v.w)
                 : "memory");
}
__device__ __forceinline__ void red_add_f(float* addr, float v) {
    asm volatile("red.global.add.f32 [%0], %1;" :: "l"(addr), "f"(v) : "memory");
}

// ---------------- phase 1 (both edge lists in one launch) ----------------
__global__ __launch_bounds__(256)
void phase1all(const float* __restrict__ x_c, const float* __restrict__ x_t,
               const float* __restrict__ x_p,
               const int* __restrict__ em_src, const int* __restrict__ em_dst,
               const int* __restrict__ ei_src, const int* __restrict__ ei_dst,
               float* __restrict__ scr) {
    int g = blockIdx.x * blockDim.x + threadIdx.x;
    int e = g >> 1, h = g & 1;
    const float* xs; const float* xd;
    const int* src; const int* dst;
    float *aggd, *aggs, *cntd, *cnts;
    if (e < EM) {
        xs = x_c; xd = x_t; src = em_src; dst = em_dst;
        aggd = scr + OFF_MTC; aggs = scr + OFF_MCS;
        cntd = scr + OFF_CMT; cnts = scr + OFF_CMC;
    } else if (e < EM + EI) {
        e -= EM;
        xs = x_p; xd = x_t; src = ei_src; dst = ei_dst;
        aggd = scr + OFF_MTP; aggs = scr + OFF_MPS;
        cntd = scr + OFF_CIT; cnts = scr + OFF_CIP;
    } else return;
    int s = __ldg(src + e);
    int d = __ldg(dst + e);
    float4 vs = ((const float4*)(xs + (size_t)s * 8))[h];
    float4 vd = ((const float4*)(xd + (size_t)d * 8))[h];
    red_add_v4(aggd + (size_t)d * 8 + h * 4, vs);
    red_add_v4(aggs + (size_t)s * 8 + h * 4, vd);
    if (h == 0) {
        red_add_f(cntd + d, 1.0f);
        red_add_f(cnts + s, 1.0f);
    }
}

// ---------------- phase 2 (both edge lists in one launch) ----------------
__global__ __launch_bounds__(256)
void phase2all(const int* __restrict__ em_src, const int* __restrict__ em_dst,
               const int* __restrict__ ei_src, const int* __restrict__ ei_dst,
               float* __restrict__ scr) {
    int g = blockIdx.x * blockDim.x + threadIdx.x;
    int e = g >> 1, h = g & 1;
    const float* msum; const float* cnt;
    const int* src; const int* dst;
    float *mm, *fd;
    if (e < EM) {
        msum = scr + OFF_MCS; cnt = scr + OFF_CMC;
        src = em_src; dst = em_dst;
        mm = scr + OFF_MMC; fd = scr + OFF_FDC;
    } else if (e < EM + EI) {
        e -= EM;
        msum = scr + OFF_MPS; cnt = scr + OFF_CIP;
        src = ei_src; dst = ei_dst;
        mm = scr + OFF_MMP; fd = scr + OFF_FDP;
    } else return;
    int s = __ldg(src + e);
    int d = __ldg(dst + e);
    float c  = __ldg(cnt + s);
    float iv = 1.0f / fmaxf(c, 1.0f);
    float4 v = ((const float4*)(msum + (size_t)s * 8))[h];
    v.x *= iv; v.y *= iv; v.z *= iv; v.w *= iv;
    red_add_v4(mm + (size_t)d * 8 + h * 4, v);
    if (h == 0) red_add_f(fd + d, c > 0.f ? 1.0f : 0.0f);
}

// ---------------- final: 44-feature linear model + softmax ----------------
__global__ __launch_bounds__(256)
void final_kernel(const float* __restrict__ xt, float* __restrict__ out) {
    __shared__ float sG[400];
    __shared__ float sg[50];
    int tid = threadIdx.x;
    for (int i = tid; i < 400; i += 256) sG[i] = g_G[i];
    if (tid < 50) sg[tid] = g_g[tid];
    __syncthreads();

    int t = blockIdx.x * 256 + tid;
    if (t >= NT) return;

    float cm = g_scr[OFF_CMT + t], ci = g_scr[OFF_CIT + t];
    float im = 1.f / fmaxf(cm, 1.f);
    float ii = 1.f / fmaxf(ci, 1.f);
    float dm = cm > 0.f ? 1.f : 0.f;
    float di = ci > 0.f ? 1.f : 0.f;

    float feat[40];
    {
        const float4* p;
        float4 a, b;
        p = (const float4*)(xt + (size_t)t * 8); a = p[0]; b = p[1];
        feat[0]=a.x; feat[1]=a.y; feat[2]=a.z; feat[3]=a.w;
        feat[4]=b.x; feat[5]=b.y; feat[6]=b.z; feat[7]=b.w;
        p = (const float4*)(g_scr + OFF_MTC + (size_t)t * 8); a = p[0]; b = p[1];
        feat[8]=a.x*im; feat[9]=a.y*im; feat[10]=a.z*im; feat[11]=a.w*im;
        feat[12]=b.x*im; feat[13]=b.y*im; feat[14]=b.z*im; feat[15]=b.w*im;
        p = (const float4*)(g_scr + OFF_MTP + (size_t)t * 8); a = p[0]; b = p[1];
        feat[16]=a.x*ii; feat[17]=a.y*ii; feat[18]=a.z*ii; feat[19]=a.w*ii;
        feat[20]=b.x*ii; feat[21]=b.y*ii; feat[22]=b.z*ii; feat[23]=b.w*ii;
        p = (const float4*)(g_scr + OFF_MMC + (size_t)t * 8); a = p[0]; b = p[1];
        feat[24]=a.x*im; feat[25]=a.y*im; feat[26]=a.z*im; feat[27]=a.w*im;
        feat[28]=b.x*im; feat[29]=b.y*im; feat[30]=b.z*im; feat[31]=b.w*im;
        p = (const float4*)(g_scr + OFF_MMP + (size_t)t * 8); a = p[0]; b = p[1];
        feat[32]=a.x*ii; feat[33]=a.y*ii; feat[34]=a.z*ii; feat[35]=a.w*ii;
        feat[36]=b.x*ii; feat[37]=b.y*ii; feat[38]=b.z*ii; feat[39]=b.w*ii;
    }
    float fdc = g_scr[OFF_FDC + t] * im;
    float fdp = g_scr[OFF_FDP + t] * ii;

    float p[NOUT];
    #pragma unroll
    for (int o = 0; o < NOUT; o++) {
        float s = sg[40 + o];
        s = fmaf(fdc, sg[o],      s);
        s = fmaf(fdp, sg[10 + o], s);
        s = fmaf(dm,  sg[20 + o], s);
        s = fmaf(di,  sg[30 + o], s);
        p[o] = s;
    }
    #pragma unroll
    for (int f = 0; f < 40; f++) {
        float xv = feat[f];
        #pragma unroll
        for (int o = 0; o < NOUT; o++) p[o] = fmaf(xv, sG[f * 10 + o], p[o]);
    }

    float m = p[0];
    #pragma unroll
    for (int o = 1; o < NOUT; o++) m = fmaxf(m, p[o]);
    float sum = 0.f;
    #pragma unroll
    for (int o = 0; o < NOUT; o++) { p[o] = expf(p[o] - m); sum += p[o]; }
    float isum = 1.0f / sum;
    #pragma unroll
    for (int o = 0; o < NOUT; o++) out[(size_t)t * NOUT + o] = p[o] * isum;
}

// ---------------- host orchestration ----------------
extern "C" void kernel_launch(void* const* d_in, const int* in_sizes, int n_in,
                              void* d_out, int out_size) {
    const float* x_c   = (const float*)d_in[0];
    const float* x_t   = (const float*)d_in[1];
    const float* x_p   = (const float*)d_in[2];
    const float* W_col = (const float*)d_in[3];
    const float* b_col = (const float*)d_in[4];
    const float* Wn    = (const float*)d_in[5];
    const float* Wr    = (const float*)d_in[6];
    const float* b_lin = (const float*)d_in[7];
    const float* W_out = (const float*)d_in[8];
    const float* b_out = (const float*)d_in[9];
    const int* em_src  = (const int*)d_in[10];
    const int* em_dst  = (const int*)d_in[11];
    const int* ei_src  = (const int*)d_in[12];
    const int* ei_dst  = (const int*)d_in[13];
    float* out = (float*)d_out;

    float* scr;
    cudaGetSymbolAddress((void**)&scr, g_scr);

    // 1) zero all accumulators
    cudaMemsetAsync(scr, 0, SCR_TOTAL * sizeof(float));

    // 2) closed-form weight chain (wide grids — no latency traps)
    prep1<<<14, 128>>>(W_col, b_col, Wn, Wr, b_lin);
    prep2<<<45, 128>>>(Wn, Wr, b_lin);
    prep3<<<1, 512>>>(W_out, b_out);

    // 3) phase-1: both edge lists, one launch
    phase1all<<<(2 * (EM + EI) + 255) / 256, 256>>>(x_c, x_t, x_p,
                                                    em_src, em_dst, ei_src, ei_dst, scr);

    // 4) phase-2: both edge lists, one launch
    phase2all<<<(2 * (EM + EI) + 255) / 256, 256>>>(em_src, em_dst, ei_src, ei_dst, scr);

    // 5) final linear model + softmax
    final_kernel<<<(NT + 255) / 256, 256>>>(x_t, out);
}

// round 8
// speedup vs baseline: 31.7766x; 1.2494x over previous
#include <cuda_runtime.h>

// ---------------- problem sizes ----------------
#define NC 100000
#define NT 300000
#define NP 50000
#define EM 300000
#define EI 600000
#define NOUT 10

// ---------------- one contiguous zeroed scratch block ----------------
#define OFF_MTC   0                               // [NT*8] sum x_c over t's customers
#define OFF_MTP   (OFF_MTC + (size_t)NT * 8)      // [NT*8] sum x_p over t's products
#define OFF_MMC   (OFF_MTP + (size_t)NT * 8)      // [NT*8] sum m_c over t's customers
#define OFF_MMP   (OFF_MMC + (size_t)NT * 8)      // [NT*8] sum m_p over t's products
#define OFF_MCS   (OFF_MMP + (size_t)NT * 8)      // [NC*8] sum x_t over c's transactions
#define OFF_MPS   (OFF_MCS + (size_t)NC * 8)      // [NP*8] sum x_t over p's transactions
#define OFF_CMT   (OFF_MPS + (size_t)NP * 8)      // [NT] deg(t, makes)
#define OFF_CIT   (OFF_CMT + NT)                  // [NT] deg(t, in)
#define OFF_CMC   (OFF_CIT + NT)                  // [NC] deg(c)
#define OFF_CIP   (OFF_CMC + NC)                  // [NP] deg(p)
#define OFF_FDC   (OFF_CIP + NP)                  // [NT] sum delta_c
#define OFF_FDP   (OFF_FDC + NT)                  // [NT] sum delta_p
#define SCR_TOTAL (OFF_FDP + NT)

__device__ float g_scr[SCR_TOTAL];

// ---------------- weight-prep scratch ----------------
__device__ float g_m1[7][1024];
__device__ float g_r1[7][128];
__device__ float g_m2[5][1024];
__device__ float g_r2[5][128];
__device__ float g_G[400];
__device__ float g_g[50];

// ---------------- weight prep (parallelized closed-form chain) ----------------
__global__ void prep1(const float* __restrict__ Wc, const float* __restrict__ bc,
                      const float* __restrict__ Wn, const float* __restrict__ Wr,
                      const float* __restrict__ bl) {
    int b = blockIdx.x, col = threadIdx.x;   // 128 threads
    if (b < 7) {
        int X = 0; const float* M1 = Wn; const float* M2 = nullptr; float s = 1.f;
        switch (b) {
            case 0: X = 1; M1 = Wr;             M2 = Wr + 2 * 16384; s = 0.5f; break;
            case 1: X = 0; M1 = Wn;             s = 0.5f; break;
            case 2: X = 2; M1 = Wn + 2 * 16384; s = 0.5f; break;
            case 3: X = 0; M1 = Wr + 1 * 16384; break;
            case 4: X = 1; M1 = Wn + 1 * 16384; break;
            case 5: X = 2; M1 = Wr + 3 * 16384; break;
            case 6: X = 1; M1 = Wn + 3 * 16384; break;
        }
        #pragma unroll 2
        for (int f = 0; f < 8; f++) {
            float acc = 0.f;
            #pragma unroll 4
            for (int d = 0; d < 16; d++) {
                int k = f * 16 + d;
                float m = M1[k * 128 + col];
                if (M2) m += M2[k * 128 + col];
                acc += Wc[X * 128 + k] * m;
            }
            g_m1[b][f * 128 + col] = s * acc;
        }
    } else {
        int r = b - 7;
        float acc = 0.f;
        switch (r) {
            case 0:
                #pragma unroll 8
                for (int k = 0; k < 128; k++) acc += bc[k] * Wn[k * 128 + col];
                g_r1[0][col] = 0.5f * acc; break;
            case 1:
                #pragma unroll 8
                for (int k = 0; k < 128; k++) acc += bc[256 + k] * Wn[2 * 16384 + k * 128 + col];
                g_r1[1][col] = 0.5f * acc; break;
            case 2:
                #pragma unroll 8
                for (int k = 0; k < 128; k++)
                    acc += bc[128 + k] * (Wr[k * 128 + col] + Wr[2 * 16384 + k * 128 + col]);
                g_r1[2][col] = 0.5f * (acc + bl[0 * 128 + col] + bl[2 * 128 + col]); break;
            case 3:
                #pragma unroll 8
                for (int k = 0; k < 128; k++) acc += bc[128 + k] * Wn[1 * 16384 + k * 128 + col];
                g_r1[3][col] = acc; break;
            case 4:
                #pragma unroll 8
                for (int k = 0; k < 128; k++) acc += bc[k] * Wr[1 * 16384 + k * 128 + col];
                g_r1[4][col] = acc + bl[1 * 128 + col]; break;
            case 5:
                #pragma unroll 8
                for (int k = 0; k < 128; k++) acc += bc[128 + k] * Wn[3 * 16384 + k * 128 + col];
                g_r1[5][col] = acc; break;
            case 6:
                #pragma unroll 8
                for (int k = 0; k < 128; k++) acc += bc[256 + k] * Wr[3 * 16384 + k * 128 + col];
                g_r1[6][col] = acc + bl[3 * 128 + col]; break;
        }
    }
}

__global__ void prep2(const float* __restrict__ Wn, const float* __restrict__ Wr,
                      const float* __restrict__ bl) {
    int b = blockIdx.x, col = threadIdx.x;   // 128 threads
    const float* Un = Wn + 4 * 16384;
    const float* Vn = Wn + 6 * 16384;
    const float* R0 = Wr + 4 * 16384;
    const float* R2 = Wr + 6 * 16384;
    if (b < 40) {
        int m = b >> 3, f = b & 7;
        float acc = 0.f;
        #pragma unroll 4
        for (int k = 0; k < 128; k++) {
            float w = 0.f;
            switch (m) {
                case 0: w = g_m1[0][f * 128 + k] * 0.5f * (R0[k * 128 + col] + R2[k * 128 + col]); break;
                case 1: w = g_m1[3][f * 128 + k] * 0.5f * Un[k * 128 + col]
                          + g_m1[1][f * 128 + k] * 0.5f * (R0[k * 128 + col] + R2[k * 128 + col]); break;
                case 2: w = g_m1[5][f * 128 + k] * 0.5f * Vn[k * 128 + col]
                          + g_m1[2][f * 128 + k] * 0.5f * (R0[k * 128 + col] + R2[k * 128 + col]); break;
                case 3: w = g_m1[4][f * 128 + k] * 0.5f * Un[k * 128 + col]; break;
                case 4: w = g_m1[6][f * 128 + k] * 0.5f * Vn[k * 128 + col]; break;
            }
            acc += w;
        }
        g_m2[m][f * 128 + col] = acc;
    } else {
        int r = b - 40;
        float acc = 0.f;
        #pragma unroll 4
        for (int k = 0; k < 128; k++) {
            float U = 0.5f * Un[k * 128 + col];
            float V = 0.5f * Vn[k * 128 + col];
            float R = 0.5f * (R0[k * 128 + col] + R2[k * 128 + col]);
            switch (r) {
                case 0: acc += g_r1[3][k] * U; break;
                case 1: acc += g_r1[5][k] * V; break;
                case 2: acc += g_r1[4][k] * U + g_r1[0][k] * R; break;
                case 3: acc += g_r1[6][k] * V + g_r1[1][k] * R; break;
                case 4: acc += g_r1[2][k] * R; break;
            }
        }
        if (r == 4) acc += 0.5f * (bl[4 * 128 + col] + bl[6 * 128 + col]);
        g_r2[r][col] = acc;
    }
}

__global__ void prep3(const float* __restrict__ Wout, const float* __restrict__ bout) {
    int tid = threadIdx.x;   // 512
    if (tid < 400) {
        int m = tid / 80, f = (tid % 80) / 10, o = tid % 10;
        float acc = 0.f;
        #pragma unroll 8
        for (int k = 0; k < 128; k++) acc += g_m2[m][f * 128 + k] * Wout[k * 10 + o];
        g_G[(m * 8 + f) * 10 + o] = acc;
    } else if (tid < 450) {
        int r = (tid - 400) / 10, o = (tid - 400) % 10;
        float acc = 0.f;
        #pragma unroll 8
        for (int k = 0; k < 128; k++) acc += g_r2[r][k] * Wout[k * 10 + o];
        if (r == 4) acc += bout[o];
        g_g[r * 10 + o] = acc;
    }
}

// ---------------- atomics ----------------
__device__ __forceinline__ void red_add_v4(float* addr, float4 v) {
    asm volatile("red.global.add.v4.f32 [%0], {%1,%2,%3,%4};"
                 :: "l"(addr), "f"(v.x), "f"(v.y), "f"(v.z), "f"(v.w)
                 : "memory");
}
__device__ __forceinline__ void red_add_f(float* addr, float v) {
    asm volatile("red.global.add.f32 [%0], %1;" :: "l"(addr), "f"(v) : "memory");
}

// ---------------- phase 1: one thread per edge, both lists ----------------
__global__ __launch_bounds__(256)
void phase1all(const float* __restrict__ x_c, const float* __restrict__ x_t,
               const float* __restrict__ x_p,
               const int* __restrict__ em_src, const int* __restrict__ em_dst,
               const int* __restrict__ ei_src, const int* __restrict__ ei_dst,
               float* __restrict__ scr) {
    int e = blockIdx.x * blockDim.x + threadIdx.x;
    const float* xs; const float* xd;
    const int* src; const int* dst;
    float *aggd, *aggs, *cntd, *cnts;
    if (e < EM) {
        xs = x_c; xd = x_t; src = em_src; dst = em_dst;
        aggd = scr + OFF_MTC; aggs = scr + OFF_MCS;
        cntd = scr + OFF_CMT; cnts = scr + OFF_CMC;
    } else if (e < EM + EI) {
        e -= EM;
        xs = x_p; xd = x_t; src = ei_src; dst = ei_dst;
        aggd = scr + OFF_MTP; aggs = scr + OFF_MPS;
        cntd = scr + OFF_CIT; cnts = scr + OFF_CIP;
    } else return;
    int s = __ldg(src + e);
    int d = __ldg(dst + e);
    const float4* ps = (const float4*)(xs + (size_t)s * 8);
    const float4* pd = (const float4*)(xd + (size_t)d * 8);
    float4 a0 = ps[0], a1 = ps[1];
    float4 b0 = pd[0], b1 = pd[1];
    float* od = aggd + (size_t)d * 8;
    float* os = aggs + (size_t)s * 8;
    red_add_v4(od,     a0);
    red_add_v4(od + 4, a1);
    red_add_v4(os,     b0);
    red_add_v4(os + 4, b1);
    red_add_f(cntd + d, 1.0f);
    red_add_f(cnts + s, 1.0f);
}

// ---------------- phase 2: one thread per edge, both lists ----------------
__global__ __launch_bounds__(256)
void phase2all(const int* __restrict__ em_src, const int* __restrict__ em_dst,
               const int* __restrict__ ei_src, const int* __restrict__ ei_dst,
               float* __restrict__ scr) {
    int e = blockIdx.x * blockDim.x + threadIdx.x;
    const float* msum; const float* cnt;
    const int* src; const int* dst;
    float *mm, *fd;
    if (e < EM) {
        msum = scr + OFF_MCS; cnt = scr + OFF_CMC;
        src = em_src; dst = em_dst;
        mm = scr + OFF_MMC; fd = scr + OFF_FDC;
    } else if (e < EM + EI) {
        e -= EM;
        msum = scr + OFF_MPS; cnt = scr + OFF_CIP;
        src = ei_src; dst = ei_dst;
        mm = scr + OFF_MMP; fd = scr + OFF_FDP;
    } else return;
    int s = __ldg(src + e);
    int d = __ldg(dst + e);
    float c  = __ldg(cnt + s);
    float iv = 1.0f / fmaxf(c, 1.0f);
    const float4* pm = (const float4*)(msum + (size_t)s * 8);
    float4 v0 = pm[0], v1 = pm[1];
    v0.x *= iv; v0.y *= iv; v0.z *= iv; v0.w *= iv;
    v1.x *= iv; v1.y *= iv; v1.z *= iv; v1.w *= iv;
    float* om = mm + (size_t)d * 8;
    red_add_v4(om,     v0);
    red_add_v4(om + 4, v1);
    red_add_f(fd + d, c > 0.f ? 1.0f : 0.0f);
}

// ---------------- final: 44-feature linear model + softmax ----------------
__global__ __launch_bounds__(256)
void final_kernel(const float* __restrict__ xt, float* __restrict__ out) {
    __shared__ float sG[400];
    __shared__ float sg[50];
    int tid = threadIdx.x;
    for (int i = tid; i < 400; i += 256) sG[i] = g_G[i];
    if (tid < 50) sg[tid] = g_g[tid];
    __syncthreads();

    int t = blockIdx.x * 256 + tid;
    if (t >= NT) return;

    float cm = g_scr[OFF_CMT + t], ci = g_scr[OFF_CIT + t];
    float im = 1.f / fmaxf(cm, 1.f);
    float ii = 1.f / fmaxf(ci, 1.f);
    float dm = cm > 0.f ? 1.f : 0.f;
    float di = ci > 0.f ? 1.f : 0.f;

    float feat[40];
    {
        const float4* p;
        float4 a, b;
        p = (const float4*)(xt + (size_t)t * 8); a = p[0]; b = p[1];
        feat[0]=a.x; feat[1]=a.y; feat[2]=a.z; feat[3]=a.w;
        feat[4]=b.x; feat[5]=b.y; feat[6]=b.z; feat[7]=b.w;
        p = (const float4*)(g_scr + OFF_MTC + (size_t)t * 8); a = p[0]; b = p[1];
        feat[8]=a.x*im; feat[9]=a.y*im; feat[10]=a.z*im; feat[11]=a.w*im;
        feat[12]=b.x*im; feat[13]=b.y*im; feat[14]=b.z*im; feat[15]=b.w*im;
        p = (const float4*)(g_scr + OFF_MTP + (size_t)t * 8); a = p[0]; b = p[1];
        feat[16]=a.x*ii; feat[17]=a.y*ii; feat[18]=a.z*ii; feat[19]=a.w*ii;
        feat[20]=b.x*ii; feat[21]=b.y*ii; feat[22]=b.z*ii; feat[23]=b.w*ii;
        p = (const float4*)(g_scr + OFF_MMC + (size_t)t * 8); a = p[0]; b = p[1];
        feat[24]=a.x*im; feat[25]=a.y*im; feat[26]=a.z*im; feat[27]=a.w*im;
        feat[28]=b.x*im; feat[29]=b.y*im; feat[30]=b.z*im; feat[31]=b.w*im;
        p = (const float4*)(g_scr + OFF_MMP + (size_t)t * 8); a = p[0]; b = p[1];
        feat[32]=a.x*ii; feat[33]=a.y*ii; feat[34]=a.z*ii; feat[35]=a.w*ii;
        feat[36]=b.x*ii; feat[37]=b.y*ii; feat[38]=b.z*ii; feat[39]=b.w*ii;
    }
    float fdc = g_scr[OFF_FDC + t] * im;
    float fdp = g_scr[OFF_FDP + t] * ii;

    float p[NOUT];
    #pragma unroll
    for (int o = 0; o < NOUT; o++) {
        float s = sg[40 + o];
        s = fmaf(fdc, sg[o],      s);
        s = fmaf(fdp, sg[10 + o], s);
        s = fmaf(dm,  sg[20 + o], s);
        s = fmaf(di,  sg[30 + o], s);
        p[o] = s;
    }
    #pragma unroll
    for (int f = 0; f < 40; f++) {
        float xv = feat[f];
        #pragma unroll
        for (int o = 0; o < NOUT; o++) p[o] = fmaf(xv, sG[f * 10 + o], p[o]);
    }

    float m = p[0];
    #pragma unroll
    for (int o = 1; o < NOUT; o++) m = fmaxf(m, p[o]);
    float sum = 0.f;
    #pragma unroll
    for (int o = 0; o < NOUT; o++) { p[o] = expf(p[o] - m); sum += p[o]; }
    float isum = 1.0f / sum;
    #pragma unroll
    for (int o = 0; o < NOUT; o++) out[(size_t)t * NOUT + o] = p[o] * isum;
}

// ---------------- host orchestration ----------------
extern "C" void kernel_launch(void* const* d_in, const int* in_sizes, int n_in,
                              void* d_out, int out_size) {
    const float* x_c   = (const float*)d_in[0];
    const float* x_t   = (const float*)d_in[1];
    const float* x_p   = (const float*)d_in[2];
    const float* W_col = (const float*)d_in[3];
    const float* b_col = (const float*)d_in[4];
    const float* Wn    = (const float*)d_in[5];
    const float* Wr    = (const float*)d_in[6];
    const float* b_lin = (const float*)d_in[7];
    const float* W_out = (const float*)d_in[8];
    const float* b_out = (const float*)d_in[9];
    const int* em_src  = (const int*)d_in[10];
    const int* em_dst  = (const int*)d_in[11];
    const int* ei_src  = (const int*)d_in[12];
    const int* ei_dst  = (const int*)d_in[13];
    float* out = (float*)d_out;

    float* scr;
    cudaGetSymbolAddress((void**)&scr, g_scr);

    // fork a side stream for the weight-prep chain (independent of the
    // memset->phase1->phase2 pipeline; joined before final_kernel)
    cudaStream_t s2;
    cudaEvent_t evFork, evJoin;
    bool forked = (cudaStreamCreateWithFlags(&s2, cudaStreamNonBlocking) == cudaSuccess) &&
                  (cudaEventCreateWithFlags(&evFork, cudaEventDisableTiming) == cudaSuccess) &&
                  (cudaEventCreateWithFlags(&evJoin, cudaEventDisableTiming) == cudaSuccess);

    if (forked) {
        cudaEventRecord(evFork, 0);
        cudaStreamWaitEvent(s2, evFork, 0);
        prep1<<<14, 128, 0, s2>>>(W_col, b_col, Wn, Wr, b_lin);
        prep2<<<45, 128, 0, s2>>>(Wn, Wr, b_lin);
        prep3<<<1, 512, 0, s2>>>(W_out, b_out);
        cudaEventRecord(evJoin, s2);
    } else {
        prep1<<<14, 128>>>(W_col, b_col, Wn, Wr, b_lin);
        prep2<<<45, 128>>>(Wn, Wr, b_lin);
        prep3<<<1, 512>>>(W_out, b_out);
    }

    // main pipeline
    cudaMemsetAsync(scr, 0, SCR_TOTAL * sizeof(float));
    phase1all<<<(EM + EI + 255) / 256, 256>>>(x_c, x_t, x_p,
                                              em_src, em_dst, ei_src, ei_dst, scr);
    phase2all<<<(EM + EI + 255) / 256, 256>>>(em_src, em_dst, ei_src, ei_dst, scr);

    if (forked) {
        cudaStreamWaitEvent(0, evJoin, 0);   // join preps before final
    }
    final_kernel<<<(NT + 255) / 256, 256>>>(x_t, out);

    if (forked) {
        cudaStreamDestroy(s2);
        cudaEventDestroy(evFork);
        cudaEventDestroy(evJoin);
    }
}

// round 9
// speedup vs baseline: 34.2804x; 1.0788x over previous
#include <cuda_runtime.h>

// ---------------- problem sizes ----------------
#define NC 100000
#define NT 300000
#define NP 50000
#define EM 300000
#define EI 600000
#define ET (EM + EI)
#define EH (ET / 2)        // 450000
#define NOUT 10

// ---------------- scratch: zone A (phase1 targets) then zone B (phase2 targets) ----------------
#define OFF_MTC   0                               // [NT*8]
#define OFF_MTP   (OFF_MTC + (size_t)NT * 8)      // [NT*8]
#define OFF_MCS   (OFF_MTP + (size_t)NT * 8)      // [NC*8]
#define OFF_MPS   (OFF_MCS + (size_t)NC * 8)      // [NP*8]
#define OFF_CMT   (OFF_MPS + (size_t)NP * 8)      // [NT]
#define OFF_CIT   (OFF_CMT + NT)                  // [NT]
#define OFF_CMC   (OFF_CIT + NT)                  // [NC]
#define OFF_CIP   (OFF_CMC + NC)                  // [NP]
#define ZONEA_END (OFF_CIP + NP)
#define OFF_MMC   ZONEA_END                       // [NT*8]
#define OFF_MMP   (OFF_MMC + (size_t)NT * 8)      // [NT*8]
#define SCR_TOTAL (OFF_MMP + (size_t)NT * 8)

__device__ float g_scr[SCR_TOTAL];

// ---------------- weight-prep scratch ----------------
__device__ float g_m1[7][1024];
__device__ float g_r1[7][128];
__device__ float g_m2[5][1024];
__device__ float g_r2[5][128];
__device__ float g_G[400];
__device__ float g_g[50];

// ---------------- weight prep (parallelized closed-form chain) ----------------
__global__ void prep1(const float* __restrict__ Wc, const float* __restrict__ bc,
                      const float* __restrict__ Wn, const float* __restrict__ Wr,
                      const float* __restrict__ bl) {
    int b = blockIdx.x, col = threadIdx.x;   // 128 threads
    if (b < 7) {
        int X = 0; const float* M1 = Wn; const float* M2 = nullptr; float s = 1.f;
        switch (b) {
            case 0: X = 1; M1 = Wr;             M2 = Wr + 2 * 16384; s = 0.5f; break;
            case 1: X = 0; M1 = Wn;             s = 0.5f; break;
            case 2: X = 2; M1 = Wn + 2 * 16384; s = 0.5f; break;
            case 3: X = 0; M1 = Wr + 1 * 16384; break;
            case 4: X = 1; M1 = Wn + 1 * 16384; break;
            case 5: X = 2; M1 = Wr + 3 * 16384; break;
            case 6: X = 1; M1 = Wn + 3 * 16384; break;
        }
        #pragma unroll 2
        for (int f = 0; f < 8; f++) {
            float acc = 0.f;
            #pragma unroll 4
            for (int d = 0; d < 16; d++) {
                int k = f * 16 + d;
                float m = M1[k * 128 + col];
                if (M2) m += M2[k * 128 + col];
                acc += Wc[X * 128 + k] * m;
            }
            g_m1[b][f * 128 + col] = s * acc;
        }
    } else {
        int r = b - 7;
        float acc = 0.f;
        switch (r) {
            case 0:
                #pragma unroll 8
                for (int k = 0; k < 128; k++) acc += bc[k] * Wn[k * 128 + col];
                g_r1[0][col] = 0.5f * acc; break;
            case 1:
                #pragma unroll 8
                for (int k = 0; k < 128; k++) acc += bc[256 + k] * Wn[2 * 16384 + k * 128 + col];
                g_r1[1][col] = 0.5f * acc; break;
            case 2:
                #pragma unroll 8
                for (int k = 0; k < 128; k++)
                    acc += bc[128 + k] * (Wr[k * 128 + col] + Wr[2 * 16384 + k * 128 + col]);
                g_r1[2][col] = 0.5f * (acc + bl[0 * 128 + col] + bl[2 * 128 + col]); break;
            case 3:
                #pragma unroll 8
                for (int k = 0; k < 128; k++) acc += bc[128 + k] * Wn[1 * 16384 + k * 128 + col];
                g_r1[3][col] = acc; break;
            case 4:
                #pragma unroll 8
                for (int k = 0; k < 128; k++) acc += bc[k] * Wr[1 * 16384 + k * 128 + col];
                g_r1[4][col] = acc + bl[1 * 128 + col]; break;
            case 5:
                #pragma unroll 8
                for (int k = 0; k < 128; k++) acc += bc[128 + k] * Wn[3 * 16384 + k * 128 + col];
                g_r1[5][col] = acc; break;
            case 6:
                #pragma unroll 8
                for (int k = 0; k < 128; k++) acc += bc[256 + k] * Wr[3 * 16384 + k * 128 + col];
                g_r1[6][col] = acc + bl[3 * 128 + col]; break;
        }
    }
}

__global__ void prep2(const float* __restrict__ Wn, const float* __restrict__ Wr,
                      const float* __restrict__ bl) {
    int b = blockIdx.x, col = threadIdx.x;   // 128 threads
    const float* Un = Wn + 4 * 16384;
    const float* Vn = Wn + 6 * 16384;
    const float* R0 = Wr + 4 * 16384;
    const float* R2 = Wr + 6 * 16384;
    if (b < 40) {
        int m = b >> 3, f = b & 7;
        float acc = 0.f;
        #pragma unroll 4
        for (int k = 0; k < 128; k++) {
            float w = 0.f;
            switch (m) {
                case 0: w = g_m1[0][f * 128 + k] * 0.5f * (R0[k * 128 + col] + R2[k * 128 + col]); break;
                case 1: w = g_m1[3][f * 128 + k] * 0.5f * Un[k * 128 + col]
                          + g_m1[1][f * 128 + k] * 0.5f * (R0[k * 128 + col] + R2[k * 128 + col]); break;
                case 2: w = g_m1[5][f * 128 + k] * 0.5f * Vn[k * 128 + col]
                          + g_m1[2][f * 128 + k] * 0.5f * (R0[k * 128 + col] + R2[k * 128 + col]); break;
                case 3: w = g_m1[4][f * 128 + k] * 0.5f * Un[k * 128 + col]; break;
                case 4: w = g_m1[6][f * 128 + k] * 0.5f * Vn[k * 128 + col]; break;
            }
            acc += w;
        }
        g_m2[m][f * 128 + col] = acc;
    } else {
        int r = b - 40;
        float acc = 0.f;
        #pragma unroll 4
        for (int k = 0; k < 128; k++) {
            float U = 0.5f * Un[k * 128 + col];
            float V = 0.5f * Vn[k * 128 + col];
            float R = 0.5f * (R0[k * 128 + col] + R2[k * 128 + col]);
            switch (r) {
                case 0: acc += g_r1[3][k] * U; break;
                case 1: acc += g_r1[5][k] * V; break;
                case 2: acc += g_r1[4][k] * U + g_r1[0][k] * R; break;
                case 3: acc += g_r1[6][k] * V + g_r1[1][k] * R; break;
                case 4: acc += g_r1[2][k] * R; break;
            }
        }
        if (r == 4) acc += 0.5f * (bl[4 * 128 + col] + bl[6 * 128 + col]);
        g_r2[r][col] = acc;
    }
}

__global__ void prep3(const float* __restrict__ Wout, const float* __restrict__ bout) {
    int tid = threadIdx.x;   // 512
    if (tid < 400) {
        int m = tid / 80, f = (tid % 80) / 10, o = tid % 10;
        float acc = 0.f;
        #pragma unroll 8
        for (int k = 0; k < 128; k++) acc += g_m2[m][f * 128 + k] * Wout[k * 10 + o];
        g_G[(m * 8 + f) * 10 + o] = acc;
    } else if (tid < 450) {
        int r = (tid - 400) / 10, o = (tid - 400) % 10;
        float acc = 0.f;
        #pragma unroll 8
        for (int k = 0; k < 128; k++) acc += g_r2[r][k] * Wout[k * 10 + o];
        if (r == 4) acc += bout[o];
        g_g[r * 10 + o] = acc;
    }
}

// ---------------- atomics ----------------
__device__ __forceinline__ void red_add_v4(float* addr, float4 v) {
    asm volatile("red.global.add.v4.f32 [%0], {%1,%2,%3,%4};"
                 :: "l"(addr), "f"(v.x), "f"(v.y), "f"(v.z), "f"(v.w)
                 : "memory");
}
__device__ __forceinline__ void red_add_f(float* addr, float v) {
    asm volatile("red.global.add.f32 [%0], %1;" :: "l"(addr), "f"(v) : "memory");
}

// ---------------- phase 1: 2 edges/thread, both lists ----------------
__global__ __launch_bounds__(256)
void phase1all(const float* __restrict__ x_c, const float* __restrict__ x_t,
               const float* __restrict__ x_p,
               const int* __restrict__ em_src, const int* __restrict__ em_dst,
               const int* __restrict__ ei_src, const int* __restrict__ ei_dst,
               float* __restrict__ scr) {
    int base = blockIdx.x * blockDim.x + threadIdx.x;
    if (base >= EH) return;

    // edge A: id = base (EM if < EM else EI); edge B: id = base + EH (always EI)
    int sA, dA;
    const float *xsA, *xdA;
    float *aggdA, *aggsA, *cntdA, *cntsA;
    if (base < EM) {
        sA = __ldg(em_src + base); dA = __ldg(em_dst + base);
        xsA = x_c; xdA = x_t;
        aggdA = scr + OFF_MTC; aggsA = scr + OFF_MCS;
        cntdA = scr + OFF_CMT; cntsA = scr + OFF_CMC;
    } else {
        int e = base - EM;
        sA = __ldg(ei_src + e); dA = __ldg(ei_dst + e);
        xsA = x_p; xdA = x_t;
        aggdA = scr + OFF_MTP; aggsA = scr + OFF_MPS;
        cntdA = scr + OFF_CIT; cntsA = scr + OFF_CIP;
    }
    int eB = base + EH - EM;   // in [150000, 600000)
    int sB = __ldg(ei_src + eB), dB = __ldg(ei_dst + eB);

    // issue all gathers before any red (max MLP)
    const float4* psA = (const float4*)(xsA + (size_t)sA * 8);
    const float4* pdA = (const float4*)(xdA + (size_t)dA * 8);
    const float4* psB = (const float4*)(x_p + (size_t)sB * 8);
    const float4* pdB = (const float4*)(x_t + (size_t)dB * 8);
    float4 a0 = psA[0], a1 = psA[1];
    float4 b0 = pdA[0], b1 = pdA[1];
    float4 c0 = psB[0], c1 = psB[1];
    float4 d0 = pdB[0], d1 = pdB[1];

    float* odA = aggdA + (size_t)dA * 8;
    float* osA = aggsA + (size_t)sA * 8;
    float* odB = scr + OFF_MTP + (size_t)dB * 8;
    float* osB = scr + OFF_MPS + (size_t)sB * 8;
    red_add_v4(odA,     a0);  red_add_v4(odA + 4, a1);
    red_add_v4(osA,     b0);  red_add_v4(osA + 4, b1);
    red_add_v4(odB,     c0);  red_add_v4(odB + 4, c1);
    red_add_v4(osB,     d0);  red_add_v4(osB + 4, d1);
    red_add_f(cntdA + dA, 1.0f);
    red_add_f(cntsA + sA, 1.0f);
    red_add_f(scr + OFF_CIT + dB, 1.0f);
    red_add_f(scr + OFF_CIP + sB, 1.0f);
}

// ---------------- phase 2: 2 edges/thread, both lists (fd eliminated) ----------------
__global__ __launch_bounds__(256)
void phase2all(const int* __restrict__ em_src, const int* __restrict__ em_dst,
               const int* __restrict__ ei_src, const int* __restrict__ ei_dst,
               float* __restrict__ scr) {
    int base = blockIdx.x * blockDim.x + threadIdx.x;
    if (base >= EH) return;

    int sA, dA;
    const float *msumA, *cntA;
    float* mmA;
    if (base < EM) {
        sA = __ldg(em_src + base); dA = __ldg(em_dst + base);
        msumA = scr + OFF_MCS; cntA = scr + OFF_CMC; mmA = scr + OFF_MMC;
    } else {
        int e = base - EM;
        sA = __ldg(ei_src + e); dA = __ldg(ei_dst + e);
        msumA = scr + OFF_MPS; cntA = scr + OFF_CIP; mmA = scr + OFF_MMP;
    }
    int eB = base + EH - EM;
    int sB = __ldg(ei_src + eB), dB = __ldg(ei_dst + eB);

    float cAv = __ldg(cntA + sA);
    float cBv = __ldg(scr + OFF_CIP + sB);
    const float4* pA = (const float4*)(msumA + (size_t)sA * 8);
    const float4* pB = (const float4*)(scr + OFF_MPS + (size_t)sB * 8);
    float4 a0 = pA[0], a1 = pA[1];
    float4 b0 = pB[0], b1 = pB[1];
    float ivA = 1.0f / fmaxf(cAv, 1.0f);
    float ivB = 1.0f / fmaxf(cBv, 1.0f);
    a0.x *= ivA; a0.y *= ivA; a0.z *= ivA; a0.w *= ivA;
    a1.x *= ivA; a1.y *= ivA; a1.z *= ivA; a1.w *= ivA;
    b0.x *= ivB; b0.y *= ivB; b0.z *= ivB; b0.w *= ivB;
    b1.x *= ivB; b1.y *= ivB; b1.z *= ivB; b1.w *= ivB;

    float* oA = mmA + (size_t)dA * 8;
    float* oB = scr + OFF_MMP + (size_t)dB * 8;
    red_add_v4(oA,     a0);  red_add_v4(oA + 4, a1);
    red_add_v4(oB,     b0);  red_add_v4(oB + 4, b1);
}

// ---------------- final: 40-feature linear model + degree gates + softmax ----------------
__global__ __launch_bounds__(256)
void final_kernel(const float* __restrict__ xt, float* __restrict__ out) {
    __shared__ float sG[400];
    __shared__ float sg[50];
    int tid = threadIdx.x;
    for (int i = tid; i < 400; i += 256) sG[i] = g_G[i];
    if (tid < 50) sg[tid] = g_g[tid];
    __syncthreads();

    int t = blockIdx.x * 256 + tid;
    if (t >= NT) return;

    float cm = g_scr[OFF_CMT + t], ci = g_scr[OFF_CIT + t];
    float im = 1.f / fmaxf(cm, 1.f);
    float ii = 1.f / fmaxf(ci, 1.f);
    float dm = cm > 0.f ? 1.f : 0.f;
    float di = ci > 0.f ? 1.f : 0.f;

    float feat[40];
    {
        const float4* p;
        float4 a, b;
        p = (const float4*)(xt + (size_t)t * 8); a = p[0]; b = p[1];
        feat[0]=a.x; feat[1]=a.y; feat[2]=a.z; feat[3]=a.w;
        feat[4]=b.x; feat[5]=b.y; feat[6]=b.z; feat[7]=b.w;
        p = (const float4*)(g_scr + OFF_MTC + (size_t)t * 8); a = p[0]; b = p[1];
        feat[8]=a.x*im; feat[9]=a.y*im; feat[10]=a.z*im; feat[11]=a.w*im;
        feat[12]=b.x*im; feat[13]=b.y*im; feat[14]=b.z*im; feat[15]=b.w*im;
        p = (const float4*)(g_scr + OFF_MTP + (size_t)t * 8); a = p[0]; b = p[1];
        feat[16]=a.x*ii; feat[17]=a.y*ii; feat[18]=a.z*ii; feat[19]=a.w*ii;
        feat[20]=b.x*ii; feat[21]=b.y*ii; feat[22]=b.z*ii; feat[23]=b.w*ii;
        p = (const float4*)(g_scr + OFF_MMC + (size_t)t * 8); a = p[0]; b = p[1];
        feat[24]=a.x*im; feat[25]=a.y*im; feat[26]=a.z*im; feat[27]=a.w*im;
        feat[28]=b.x*im; feat[29]=b.y*im; feat[30]=b.z*im; feat[31]=b.w*im;
        p = (const float4*)(g_scr + OFF_MMP + (size_t)t * 8); a = p[0]; b = p[1];
        feat[32]=a.x*ii; feat[33]=a.y*ii; feat[34]=a.z*ii; feat[35]=a.w*ii;
        feat[36]=b.x*ii; feat[37]=b.y*ii; feat[38]=b.z*ii; feat[39]=b.w*ii;
    }

    float p[NOUT];
    // fd fractions are identically dm / di (every edge endpoint has deg >= 1)
    #pragma unroll
    for (int o = 0; o < NOUT; o++) {
        float s = sg[40 + o];
        s = fmaf(dm, sg[o]      + sg[20 + o], s);
        s = fmaf(di, sg[10 + o] + sg[30 + o], s);
        p[o] = s;
    }
    #pragma unroll
    for (int f = 0; f < 40; f++) {
        float xv = feat[f];
        #pragma unroll
        for (int o = 0; o < NOUT; o++) p[o] = fmaf(xv, sG[f * 10 + o], p[o]);
    }

    float m = p[0];
    #pragma unroll
    for (int o = 1; o < NOUT; o++) m = fmaxf(m, p[o]);
    float sum = 0.f;
    #pragma unroll
    for (int o = 0; o < NOUT; o++) { p[o] = expf(p[o] - m); sum += p[o]; }
    float isum = 1.0f / sum;
    #pragma unroll
    for (int o = 0; o < NOUT; o++) out[(size_t)t * NOUT + o] = p[o] * isum;
}

// ---------------- host orchestration ----------------
extern "C" void kernel_launch(void* const* d_in, const int* in_sizes, int n_in,
                              void* d_out, int out_size) {
    const float* x_c   = (const float*)d_in[0];
    const float* x_t   = (const float*)d_in[1];
    const float* x_p   = (const float*)d_in[2];
    const float* W_col = (const float*)d_in[3];
    const float* b_col = (const float*)d_in[4];
    const float* Wn    = (const float*)d_in[5];
    const float* Wr    = (const float*)d_in[6];
    const float* b_lin = (const float*)d_in[7];
    const float* W_out = (const float*)d_in[8];
    const float* b_out = (const float*)d_in[9];
    const int* em_src  = (const int*)d_in[10];
    const int* em_dst  = (const int*)d_in[11];
    const int* ei_src  = (const int*)d_in[12];
    const int* ei_dst  = (const int*)d_in[13];
    float* out = (float*)d_out;

    float* scr;
    cudaGetSymbolAddress((void**)&scr, g_scr);

    cudaStream_t s2;
    cudaEvent_t evFork, evZoneB, evJoin;
    bool forked = (cudaStreamCreateWithFlags(&s2, cudaStreamNonBlocking) == cudaSuccess) &&
                  (cudaEventCreateWithFlags(&evFork,  cudaEventDisableTiming) == cudaSuccess) &&
                  (cudaEventCreateWithFlags(&evZoneB, cudaEventDisableTiming) == cudaSuccess) &&
                  (cudaEventCreateWithFlags(&evJoin,  cudaEventDisableTiming) == cudaSuccess);

    if (forked) {
        cudaEventRecord(evFork, 0);
        cudaStreamWaitEvent(s2, evFork, 0);
        // side stream: zone-B zero (phase2 targets) + weight-prep chain
        cudaMemsetAsync(scr + ZONEA_END, 0, (SCR_TOTAL - ZONEA_END) * sizeof(float), s2);
        cudaEventRecord(evZoneB, s2);
        prep1<<<14, 128, 0, s2>>>(W_col, b_col, Wn, Wr, b_lin);
        prep2<<<45, 128, 0, s2>>>(Wn, Wr, b_lin);
        prep3<<<1, 512, 0, s2>>>(W_out, b_out);
        cudaEventRecord(evJoin, s2);

        // main stream: zone-A zero -> phase1 -> (join B) phase2 -> (join preps) final
        cudaMemsetAsync(scr, 0, ZONEA_END * sizeof(float));
        phase1all<<<(EH + 255) / 256, 256>>>(x_c, x_t, x_p,
                                             em_src, em_dst, ei_src, ei_dst, scr);
        cudaStreamWaitEvent(0, evZoneB, 0);
        phase2all<<<(EH + 255) / 256, 256>>>(em_src, em_dst, ei_src, ei_dst, scr);
        cudaStreamWaitEvent(0, evJoin, 0);
        final_kernel<<<(NT + 255) / 256, 256>>>(x_t, out);

        cudaStreamDestroy(s2);
        cudaEventDestroy(evFork);
        cudaEventDestroy(evZoneB);
        cudaEventDestroy(evJoin);
    } else {
        cudaMemsetAsync(scr, 0, SCR_TOTAL * sizeof(float));
        prep1<<<14, 128>>>(W_col, b_col, Wn, Wr, b_lin);
        prep2<<<45, 128>>>(Wn, Wr, b_lin);
        prep3<<<1, 512>>>(W_out, b_out);
        phase1all<<<(EH + 255) / 256, 256>>>(x_c, x_t, x_p,
                                             em_src, em_dst, ei_src, ei_dst, scr);
        phase2all<<<(EH + 255) / 256, 256>>>(em_src, em_dst, ei_src, ei_dst, scr);
        final_kernel<<<(NT + 255) / 256, 256>>>(x_t, out);
    }
}